// round 11
// baseline (speedup 1.0000x reference)
#include <cuda_runtime.h>
#include <cuda_bf16.h>
#include <cstdint>

// ---- problem constants ----
#define B_    8
#define N1_   8192
#define N2_   2048
#define C1_   128
#define C2_   256
#define INCH  384
#define O1_   256
#define O2_   256

// ---- device scratch ----
__device__ float g_b1eff[O1_], g_b2eff[O2_];
__device__ __align__(16) __nv_bfloat16 g_f1T_hi[(size_t)B_ * N1_ * C1_], g_f1T_lo[(size_t)B_ * N1_ * C1_];
__device__ __align__(16) __nv_bfloat16 g_f2T_hi[(size_t)B_ * N2_ * C2_], g_f2T_lo[(size_t)B_ * N2_ * C2_];
__device__ __align__(16) float g_PT[(size_t)B_ * N2_ * O1_];      // P^T [b][n2][o1]
__device__ int   g_idx[B_ * N1_ * 3];
__device__ float g_wgt[B_ * N1_ * 3];

// fragment-order packed weights (uint4 = 4 mma B-regs per lane)
// W2:  [kc 8][ks 2][warpN 4][nj 4][lane 32]                    = 8192
// W1b: [kc 4][ks 2][warpN 4][nj 4][lane 32]                    = 4096
// W1a: [nb 2][kc 8][ks 2][warpN 4][nj 2][lane 32]              = 8192
__device__ __align__(16) uint4 g_W2p_hi [8192], g_W2p_lo [8192];
__device__ __align__(16) uint4 g_W1bp_hi[4096], g_W1bp_lo[4096];
__device__ __align__(16) uint4 g_W1ap_hi[8192], g_W1ap_lo[8192];

// ============================================================
// primitives
// ============================================================
__device__ __forceinline__ uint32_t smem_u32(const void* p) {
    uint32_t a;
    asm("{ .reg .u64 t; cvta.to.shared.u64 t, %1; cvt.u32.u64 %0, t; }" : "=r"(a) : "l"(p));
    return a;
}
__device__ __forceinline__ void ldsm4(uint32_t* r, uint32_t addr) {
    asm volatile("ldmatrix.sync.aligned.m8n8.x4.shared.b16 {%0,%1,%2,%3}, [%4];"
                 : "=r"(r[0]), "=r"(r[1]), "=r"(r[2]), "=r"(r[3]) : "r"(addr));
}
__device__ __forceinline__ void mma16816(float* c, const uint32_t* a, uint32_t b0, uint32_t b1) {
    asm volatile(
        "mma.sync.aligned.m16n8k16.row.col.f32.bf16.bf16.f32 "
        "{%0,%1,%2,%3}, {%4,%5,%6,%7}, {%8,%9}, {%0,%1,%2,%3};"
        : "+f"(c[0]), "+f"(c[1]), "+f"(c[2]), "+f"(c[3])
        : "r"(a[0]), "r"(a[1]), "r"(a[2]), "r"(a[3]), "r"(b0), "r"(b1));
}
__device__ __forceinline__ uint32_t splitpack(float a, float b, uint32_t& lo) {
    __nv_bfloat16 ha = __float2bfloat16(a), hb = __float2bfloat16(b);
    __nv_bfloat16 la = __float2bfloat16(a - __bfloat162float(ha));
    __nv_bfloat16 lb = __float2bfloat16(b - __bfloat162float(hb));
    __nv_bfloat162 H2; H2.x = ha; H2.y = hb;
    __nv_bfloat162 L2; L2.x = la; L2.y = lb;
    lo = *(uint32_t*)&L2;
    return *(uint32_t*)&H2;
}
// fold+split two adjacent weights -> packed bf16x2 hi/lo words
__device__ __forceinline__ uint32_t fold2(float wa, float wb, float scale, uint32_t& lo) {
    return splitpack(wa * scale, wb * scale, lo);
}

// ============================================================
// FUSED gemm1+gemm2 (byte-identical to the R10-measured version)
// ============================================================
#define FSLD 40
#define H1P  264
#define OTP  68
#define OF_H1HI 0
#define OF_H1LO 33792
#define OF_ABUF 67584
#define OF_OUTT 0
#define FSM_BYTES 88064

__global__ void __launch_bounds__(256, 2) fused12_kernel(float* __restrict__ out) {
    extern __shared__ __align__(16) char fsm[];
    __nv_bfloat16* h1hi = (__nv_bfloat16*)(fsm + OF_H1HI);
    __nv_bfloat16* h1lo = (__nv_bfloat16*)(fsm + OF_H1LO);
    float*         outT = (float*)(fsm + OF_OUTT);

    const int tid = threadIdx.x, lane = tid & 31, wid = tid >> 5;
    const int warpM = wid >> 2, warpN = wid & 3;
    const int b = blockIdx.y;
    const int pt0 = blockIdx.x * 64;

    const uint32_t h1hiB = smem_u32(h1hi), h1loB = smem_u32(h1lo);
    const uint32_t abufB = smem_u32(fsm + OF_ABUF);

    const int lrow = tid >> 2;
    const int lcol = (tid & 3) * 8;

    const uint32_t aRowSel = lane & 15;
    const uint32_t aColSel = (lane >> 4) << 3;

    // ---------------- stage 1 ----------------
    const __nv_bfloat16* Ah = g_f1T_hi + ((size_t)b * N1_ + pt0 + lrow) * C1_ + lcol;
    const __nv_bfloat16* Al = g_f1T_lo + ((size_t)b * N1_ + pt0 + lrow) * C1_ + lcol;

    float acc[2][8][4];
    #pragma unroll
    for (int i = 0; i < 2; i++)
        #pragma unroll
        for (int j = 0; j < 8; j++)
            #pragma unroll
            for (int k = 0; k < 4; k++) acc[i][j][k] = 0.f;

    uint4 rA0 = *(const uint4*)Ah;
    uint4 rA1 = *(const uint4*)Al;

    for (int kc = 0; kc < 4; kc++) {
        uint32_t bufO = (kc & 1) * 10240u;
        *(uint4*)(fsm + OF_ABUF + bufO + (lrow * FSLD + lcol) * 2) = rA0;
        *(uint4*)(fsm + OF_ABUF + bufO + 5120 + (lrow * FSLD + lcol) * 2) = rA1;

        int nk = (kc < 3) ? (kc + 1) * 32 : 0;
        rA0 = *(const uint4*)(Ah + nk);
        rA1 = *(const uint4*)(Al + nk);

        __syncthreads();

        #pragma unroll
        for (int ks = 0; ks < 2; ks++) {
            uint4 fh[4], fl[4];
            #pragma unroll
            for (int nj = 0; nj < 4; nj++) {
                size_t o = ((((size_t)kc * 2 + ks) * 4 + warpN) * 4 + nj) * 32 + lane;
                fh[nj] = g_W1bp_hi[o];
                fl[nj] = g_W1bp_lo[o];
            }
            uint32_t ah[2][4], al[2][4];
            #pragma unroll
            for (int mi = 0; mi < 2; mi++) {
                uint32_t off = bufO + ((warpM * 32 + mi * 16 + aRowSel) * FSLD + ks * 16 + aColSel) * 2;
                ldsm4(ah[mi], abufB + off);
                ldsm4(al[mi], abufB + 5120 + off);
            }
            #pragma unroll
            for (int nj = 0; nj < 4; nj++) {
                const uint32_t* BH = (const uint32_t*)&fh[nj];
                const uint32_t* BL = (const uint32_t*)&fl[nj];
                #pragma unroll
                for (int mi = 0; mi < 2; mi++)
                    #pragma unroll
                    for (int sub = 0; sub < 2; sub++) {
                        int ni = nj * 2 + sub;
                        uint32_t b0 = BH[sub * 2], b1 = BH[sub * 2 + 1];
                        uint32_t c0_ = BL[sub * 2], c1_ = BL[sub * 2 + 1];
                        mma16816(acc[mi][ni], ah[mi], b0, b1);
                        mma16816(acc[mi][ni], ah[mi], c0_, c1_);
                        mma16816(acc[mi][ni], al[mi], b0, b1);
                    }
            }
        }
    }
    __syncthreads();

    // ---------------- epilogue 1 ----------------
    {
        const int r0 = lane >> 2;
        const int c0 = (lane & 3) * 2;
        const int*   IX = g_idx + (size_t)b * N1_ * 3;
        const float* WG = g_wgt + (size_t)b * N1_ * 3;
        const float* PT = g_PT + (size_t)b * N2_ * O1_;
        #pragma unroll
        for (int mi = 0; mi < 2; mi++)
            #pragma unroll
            for (int h = 0; h < 2; h++) {
                int gmL = warpM * 32 + mi * 16 + r0 + h * 8;
                int n = pt0 + gmL;
                int i0 = IX[n * 3], i1 = IX[n * 3 + 1], i2 = IX[n * 3 + 2];
                float w0 = WG[n * 3], w1 = WG[n * 3 + 1], w2 = WG[n * 3 + 2];
                #pragma unroll
                for (int ni = 0; ni < 8; ni++) {
                    int gn = warpN * 64 + ni * 8 + c0;
                    float2 p0 = *(const float2*)&PT[(size_t)i0 * O1_ + gn];
                    float2 p1 = *(const float2*)&PT[(size_t)i1 * O1_ + gn];
                    float2 p2 = *(const float2*)&PT[(size_t)i2 * O1_ + gn];
                    float2 bs = *(const float2*)&g_b1eff[gn];
                    float v0 = acc[mi][ni][h * 2 + 0] + bs.x + w0 * p0.x + w1 * p1.x + w2 * p2.x;
                    float v1 = acc[mi][ni][h * 2 + 1] + bs.y + w0 * p0.y + w1 * p1.y + w2 * p2.y;
                    v0 = fmaxf(v0, 0.f); v1 = fmaxf(v1, 0.f);
                    uint32_t lo, hi = splitpack(v0, v1, lo);
                    *(uint32_t*)&h1hi[gmL * H1P + gn] = hi;
                    *(uint32_t*)&h1lo[gmL * H1P + gn] = lo;
                }
            }
    }
    __syncthreads();

    // ---------------- stage 2 (no syncs) ----------------
    float acc2[2][8][4];
    #pragma unroll
    for (int i = 0; i < 2; i++)
        #pragma unroll
        for (int j = 0; j < 8; j++)
            #pragma unroll
            for (int k = 0; k < 4; k++) acc2[i][j][k] = 0.f;

    for (int kc = 0; kc < 8; kc++) {
        #pragma unroll
        for (int ks = 0; ks < 2; ks++) {
            uint4 fh[4], fl[4];
            #pragma unroll
            for (int nj = 0; nj < 4; nj++) {
                size_t o = ((((size_t)kc * 2 + ks) * 4 + warpN) * 4 + nj) * 32 + lane;
                fh[nj] = g_W2p_hi[o];
                fl[nj] = g_W2p_lo[o];
            }
            uint32_t ah[2][4], al[2][4];
            #pragma unroll
            for (int mi = 0; mi < 2; mi++) {
                uint32_t off = ((warpM * 32 + mi * 16 + aRowSel) * H1P + kc * 32 + ks * 16 + aColSel) * 2;
                ldsm4(ah[mi], h1hiB + off);
                ldsm4(al[mi], h1loB + off);
            }
            #pragma unroll
            for (int nj = 0; nj < 4; nj++) {
                const uint32_t* BH = (const uint32_t*)&fh[nj];
                const uint32_t* BL = (const uint32_t*)&fl[nj];
                #pragma unroll
                for (int mi = 0; mi < 2; mi++)
                    #pragma unroll
                    for (int sub = 0; sub < 2; sub++) {
                        int ni = nj * 2 + sub;
                        uint32_t b0 = BH[sub * 2], b1 = BH[sub * 2 + 1];
                        uint32_t c0_ = BL[sub * 2], c1_ = BL[sub * 2 + 1];
                        mma16816(acc2[mi][ni], ah[mi], b0, b1);
                        mma16816(acc2[mi][ni], ah[mi], c0_, c1_);
                        mma16816(acc2[mi][ni], al[mi], b0, b1);
                    }
            }
        }
    }
    __syncthreads();

    // ---------------- epilogue 2 ----------------
    {
        const int r0 = lane >> 2;
        const int c0 = (lane & 3) * 2;
        #pragma unroll
        for (int mi = 0; mi < 2; mi++)
            #pragma unroll
            for (int h = 0; h < 2; h++) {
                int gmL = warpM * 32 + mi * 16 + r0 + h * 8;
                #pragma unroll
                for (int ni = 0; ni < 8; ni++) {
                    int gn = warpN * 64 + ni * 8 + c0;
                    float2 bs = *(const float2*)&g_b2eff[gn];
                    outT[(size_t)gn * OTP + gmL]       = fmaxf(acc2[mi][ni][h * 2 + 0] + bs.x, 0.f);
                    outT[(size_t)(gn + 1) * OTP + gmL] = fmaxf(acc2[mi][ni][h * 2 + 1] + bs.y, 0.f);
                }
            }
    }
    __syncthreads();

    float* dst = out + (size_t)b * O2_ * N1_ + pt0;
    for (int i = tid; i < 256 * 16; i += 256) {
        int o2 = i >> 4;
        int c = (i & 15) << 2;
        uint4 v = *(uint4*)&outT[o2 * OTP + c];
        *(uint4*)(dst + (size_t)o2 * N1_ + c) = v;
    }
}

// ============================================================
// gemmP v2: PT = f2T @ W1a^T with fragment-packed W1a.
// A (f2T) ping-pong staged, ONE sync per K-chunk; no B smem at all.
// M=64 (n2), N=128 (o1, nb = blockIdx.y), K=256.
// ============================================================
__global__ void __launch_bounds__(256, 2) gemmP_kernel() {
    __shared__ __align__(16) char gsm[20480];   // 2 bufs x (hi 5120 + lo 5120)

    const int tid = threadIdx.x, lane = tid & 31, wid = tid >> 5;
    const int warpM = wid >> 2, warpN = wid & 3;
    const int b = blockIdx.z;
    const int Mbase = blockIdx.x * 64;
    const int nb = blockIdx.y;          // o1 half (0 or 1)

    float acc[2][4][4];
    #pragma unroll
    for (int i = 0; i < 2; i++)
        #pragma unroll
        for (int j = 0; j < 4; j++)
            #pragma unroll
            for (int k = 0; k < 4; k++) acc[i][j][k] = 0.f;

    const int lrow = tid >> 2;
    const int lcol = (tid & 3) * 8;

    const __nv_bfloat16* pAhi = g_f2T_hi + ((size_t)b * N2_ + Mbase + lrow) * C2_ + lcol;
    const __nv_bfloat16* pAlo = g_f2T_lo + ((size_t)b * N2_ + Mbase + lrow) * C2_ + lcol;

    const uint32_t aRowSel = lane & 15;
    const uint32_t aColSel = (lane >> 4) << 3;
    const uint32_t gsmB = smem_u32(gsm);

    uint4 rA0 = *(const uint4*)pAhi;
    uint4 rA1 = *(const uint4*)pAlo;

    for (int kc = 0; kc < 8; kc++) {
        uint32_t bufO = (kc & 1) * 10240u;
        *(uint4*)(gsm + bufO + (lrow * FSLD + lcol) * 2) = rA0;
        *(uint4*)(gsm + bufO + 5120 + (lrow * FSLD + lcol) * 2) = rA1;

        int nk = (kc < 7) ? (kc + 1) * 32 : 0;
        rA0 = *(const uint4*)(pAhi + nk);
        rA1 = *(const uint4*)(pAlo + nk);

        __syncthreads();

        #pragma unroll
        for (int ks = 0; ks < 2; ks++) {
            uint4 fh[2], fl[2];
            #pragma unroll
            for (int nj = 0; nj < 2; nj++) {
                size_t o = (((((size_t)nb * 8 + kc) * 2 + ks) * 4 + warpN) * 2 + nj) * 32 + lane;
                fh[nj] = g_W1ap_hi[o];
                fl[nj] = g_W1ap_lo[o];
            }
            uint32_t ah[2][4], al[2][4];
            #pragma unroll
            for (int mi = 0; mi < 2; mi++) {
                uint32_t off = bufO + ((warpM * 32 + mi * 16 + aRowSel) * FSLD + ks * 16 + aColSel) * 2;
                ldsm4(ah[mi], gsmB + off);
                ldsm4(al[mi], gsmB + 5120 + off);
            }
            #pragma unroll
            for (int nj = 0; nj < 2; nj++) {
                const uint32_t* BH = (const uint32_t*)&fh[nj];
                const uint32_t* BL = (const uint32_t*)&fl[nj];
                #pragma unroll
                for (int mi = 0; mi < 2; mi++)
                    #pragma unroll
                    for (int sub = 0; sub < 2; sub++) {
                        int ni = nj * 2 + sub;
                        uint32_t b0 = BH[sub * 2], b1 = BH[sub * 2 + 1];
                        uint32_t c0_ = BL[sub * 2], c1_ = BL[sub * 2 + 1];
                        mma16816(acc[mi][ni], ah[mi], b0, b1);
                        mma16816(acc[mi][ni], ah[mi], c0_, c1_);
                        mma16816(acc[mi][ni], al[mi], b0, b1);
                    }
            }
        }
    }

    const int r0 = lane >> 2;
    const int c0 = (lane & 3) * 2;
    float* outP = g_PT + (size_t)b * N2_ * O1_;
    const int Nbase = nb * 128;
    #pragma unroll
    for (int mi = 0; mi < 2; mi++)
        #pragma unroll
        for (int h = 0; h < 2; h++) {
            int gm = Mbase + warpM * 32 + mi * 16 + r0 + h * 8;
            #pragma unroll
            for (int ni = 0; ni < 4; ni++) {
                int gn = Nbase + warpN * 32 + ni * 8 + c0;
                *(float2*)&outP[(size_t)gm * O1_ + gn] =
                    make_float2(acc[mi][ni][h * 2], acc[mi][ni][h * 2 + 1]);
            }
        }
}

// ============================================================
// packknn: ONE kernel. blocks [0,128): kNN (2 pts/thread, smem staging).
// blocks [128,192): fold+split+pack W1a/W1b/W2 from RAW inputs + biases.
// ============================================================
#define KNN_BLKS 128          // (N1/512) * B = 16*8
#define PACK_BLKS 64
#define RS_ 0.99999500003749969f

__device__ __forceinline__ void knn3_insert(float dd, int m,
                                            float& d0, float& d1, float& d2,
                                            int& j0, int& j1, int& j2) {
    if (dd < d2) {
        if (dd < d1) {
            d2 = d1; j2 = j1;
            if (dd < d0) { d1 = d0; j1 = j0; d0 = dd; j0 = m; }
            else         { d1 = dd; j1 = m; }
        } else { d2 = dd; j2 = m; }
    }
}

__global__ void __launch_bounds__(256) packknn_kernel(
    const float* __restrict__ xyz1, const float* __restrict__ xyz2,
    const float* __restrict__ W1, const float* __restrict__ b1,
    const float* __restrict__ g1, const float* __restrict__ be1,
    const float* __restrict__ W2, const float* __restrict__ b2,
    const float* __restrict__ g2, const float* __restrict__ be2) {
    __shared__ __align__(16) float4 s2[N2_];
    int bid = blockIdx.x;

    if (bid < KNN_BLKS) {
        // ---- kNN: 2 points per thread ----
        int px = bid & 15, b = bid >> 4;
        const float* q = xyz2 + (size_t)b * N2_ * 3;
        for (int i = threadIdx.x; i < N2_; i += 256) {
            float ax = q[i * 3 + 0], ay = q[i * 3 + 1], az = q[i * 3 + 2];
            s2[i] = make_float4(ax, ay, az, ax * ax + ay * ay + az * az);
        }
        __syncthreads();

        int pA = px * 512 + threadIdx.x;
        int pB = pA + 256;
        const float* ppA = xyz1 + ((size_t)b * N1_ + pA) * 3;
        const float* ppB = xyz1 + ((size_t)b * N1_ + pB) * 3;
        float xA = ppA[0], yA = ppA[1], zA = ppA[2];
        float xB = ppB[0], yB = ppB[1], zB = ppB[2];
        float p2A = xA * xA + yA * yA + zA * zA;
        float p2B = xB * xB + yB * yB + zB * zB;

        float dA0 = 3.4e38f, dA1 = 3.4e38f, dA2 = 3.4e38f;
        float dB0 = 3.4e38f, dB1 = 3.4e38f, dB2 = 3.4e38f;
        int jA0 = 0, jA1 = 0, jA2 = 0, jB0 = 0, jB1 = 0, jB2 = 0;
        #pragma unroll 4
        for (int m = 0; m < N2_; m++) {
            float4 v = s2[m];
            float ddA = (p2A + v.w) - 2.0f * (xA * v.x + yA * v.y + zA * v.z);
            float ddB = (p2B + v.w) - 2.0f * (xB * v.x + yB * v.y + zB * v.z);
            knn3_insert(ddA, m, dA0, dA1, dA2, jA0, jA1, jA2);
            knn3_insert(ddB, m, dB0, dB1, dB2, jB0, jB1, jB2);
        }
        #pragma unroll
        for (int s = 0; s < 2; s++) {
            float d0 = s ? dB0 : dA0, d1 = s ? dB1 : dA1, d2 = s ? dB2 : dA2;
            int   j0 = s ? jB0 : jA0, j1 = s ? jB1 : jA1, j2 = s ? jB2 : jA2;
            int   p  = s ? pB : pA;
            float w0 = 1.0f / fmaxf(sqrtf(fmaxf(d0, 0.f)), 1e-8f);
            float w1 = 1.0f / fmaxf(sqrtf(fmaxf(d1, 0.f)), 1e-8f);
            float w2 = 1.0f / fmaxf(sqrtf(fmaxf(d2, 0.f)), 1e-8f);
            float inv = 1.0f / (w0 + w1 + w2);
            size_t base = ((size_t)b * N1_ + p) * 3;
            g_idx[base + 0] = j0; g_idx[base + 1] = j1; g_idx[base + 2] = j2;
            g_wgt[base + 0] = w0 * inv; g_wgt[base + 1] = w1 * inv; g_wgt[base + 2] = w2 * inv;
        }
        return;
    }

    // ---- pack part ----
    int t = (bid - KNN_BLKS) * 256 + threadIdx.x;
    int nt = PACK_BLKS * 256;

    // W2 packed: 8192 entries (kc8|ks|wN|nj4|lane)
    for (int i = t; i < 8192; i += nt) {
        int lane = i & 31, nj = (i >> 5) & 3, wN = (i >> 7) & 3, ks = (i >> 9) & 1, kc = i >> 10;
        int n0 = wN * 64 + nj * 16, k0 = kc * 32 + ks * 16;
        uint4 h, l;
        uint32_t* hp = (uint32_t*)&h;
        uint32_t* lp = (uint32_t*)&l;
        #pragma unroll
        for (int j = 0; j < 4; j++) {
            int n = n0 + ((j >> 1) << 3) + (lane >> 2);
            int k = k0 + ((j & 1) << 3) + (lane & 3) * 2;
            float s = g2[n] * RS_;
            hp[j] = fold2(W2[(size_t)n * O1_ + k], W2[(size_t)n * O1_ + k + 1], s, lp[j]);
        }
        g_W2p_hi[i] = h;
        g_W2p_lo[i] = l;
    }
    // W1b packed: 4096 entries (kc4|ks|wN|nj4|lane); W1 cols [256,384)
    for (int i = t; i < 4096; i += nt) {
        int lane = i & 31, nj = (i >> 5) & 3, wN = (i >> 7) & 3, ks = (i >> 9) & 1, kc = i >> 10;
        int n0 = wN * 64 + nj * 16, k0 = kc * 32 + ks * 16;
        uint4 h, l;
        uint32_t* hp = (uint32_t*)&h;
        uint32_t* lp = (uint32_t*)&l;
        #pragma unroll
        for (int j = 0; j < 4; j++) {
            int n = n0 + ((j >> 1) << 3) + (lane >> 2);
            int k = k0 + ((j & 1) << 3) + (lane & 3) * 2;
            float s = g1[n] * RS_;
            hp[j] = fold2(W1[(size_t)n * INCH + C2_ + k], W1[(size_t)n * INCH + C2_ + k + 1], s, lp[j]);
        }
        g_W1bp_hi[i] = h;
        g_W1bp_lo[i] = l;
    }
    // W1a packed: 8192 entries (nb|kc8|ks|wN|nj2|lane); W1 cols [0,256)
    for (int i = t; i < 8192; i += nt) {
        int lane = i & 31, nj = (i >> 5) & 1, wN = (i >> 6) & 3, ks = (i >> 8) & 1,
            kc = (i >> 9) & 7, nb = (i >> 12) & 1;
        int n0 = nb * 128 + wN * 32 + nj * 16, k0 = kc * 32 + ks * 16;
        uint4 h, l;
        uint32_t* hp = (uint32_t*)&h;
        uint32_t* lp = (uint32_t*)&l;
        #pragma unroll
        for (int j = 0; j < 4; j++) {
            int n = n0 + ((j >> 1) << 3) + (lane >> 2);
            int k = k0 + ((j & 1) << 3) + (lane & 3) * 2;
            float s = g1[n] * RS_;
            hp[j] = fold2(W1[(size_t)n * INCH + k], W1[(size_t)n * INCH + k + 1], s, lp[j]);
        }
        g_W1ap_hi[i] = h;
        g_W1ap_lo[i] = l;
    }
    // biases
    for (int i = t; i < O1_; i += nt) g_b1eff[i] = g1[i] * RS_ * b1[i] + be1[i];
    for (int i = t; i < O2_; i += nt) g_b2eff[i] = g2[i] * RS_ * b2[i] + be2[i];
}

// ============================================================
// tsplit: transpose + split feats1 AND feats2 (4.2KB smem)
// ============================================================
#define TS1_BLKS  ((N1_ / 32) * (C1_ / 32) * B_)      // 8192
#define TS2_BLKS  ((N2_ / 32) * (C2_ / 32) * B_)      // 4096

__device__ __forceinline__ void tsplit_tile(int n_t, int c_t, int b,
                                            const float* __restrict__ src,
                                            __nv_bfloat16* __restrict__ dhi,
                                            __nv_bfloat16* __restrict__ dlo,
                                            int C, int Np, float (*t)[33]) {
    int n0 = n_t * 32, c0 = c_t * 32;
    int tx = threadIdx.x & 31, ty = threadIdx.x >> 5;
    #pragma unroll
    for (int r = 0; r < 4; r++) {
        int c = c0 + ty + r * 8;
        t[ty + r * 8][tx] = src[((size_t)b * C + c) * Np + n0 + tx];
    }
    __syncthreads();
    #pragma unroll
    for (int r = 0; r < 4; r++) {
        int n = n0 + ty + r * 8;
        int c = c0 + tx;
        float v = t[tx][ty + r * 8];
        __nv_bfloat16 hi = __float2bfloat16(v);
        size_t o = ((size_t)b * Np + n) * C + c;
        dhi[o] = hi;
        dlo[o] = __float2bfloat16(v - __bfloat162float(hi));
    }
}

__global__ void __launch_bounds__(256) tsplit_kernel(const float* __restrict__ feats1,
                                                     const float* __restrict__ feats2) {
    __shared__ float t[32][33];
    int bid = blockIdx.x;
    if (bid < TS1_BLKS) {
        int n_t = bid & 255, c_t = (bid >> 8) & 3, b = bid >> 10;
        tsplit_tile(n_t, c_t, b, feats1, g_f1T_hi, g_f1T_lo, C1_, N1_, t);
    } else {
        bid -= TS1_BLKS;
        int n_t = bid & 63, c_t = (bid >> 6) & 7, b = bid >> 9;
        tsplit_tile(n_t, c_t, b, feats2, g_f2T_hi, g_f2T_lo, C2_, N2_, t);
    }
}

// ============================================================
extern "C" void kernel_launch(void* const* d_in, const int* in_sizes, int n_in,
                              void* d_out, int out_size) {
    const float* xyz1   = (const float*)d_in[0];
    const float* xyz2   = (const float*)d_in[1];
    const float* feats1 = (const float*)d_in[2];
    const float* feats2 = (const float*)d_in[3];
    const float* W1     = (const float*)d_in[4];
    const float* b1     = (const float*)d_in[5];
    const float* g1     = (const float*)d_in[6];
    const float* be1    = (const float*)d_in[7];
    const float* W2     = (const float*)d_in[8];
    const float* b2     = (const float*)d_in[9];
    const float* g2     = (const float*)d_in[10];
    const float* be2    = (const float*)d_in[11];
    float* out = (float*)d_out;

    cudaFuncSetAttribute(fused12_kernel, cudaFuncAttributeMaxDynamicSharedMemorySize, FSM_BYTES);

    packknn_kernel<<<KNN_BLKS + PACK_BLKS, 256>>>(xyz1, xyz2, W1, b1, g1, be1,
                                                  W2, b2, g2, be2);            // idx 0
    tsplit_kernel<<<TS1_BLKS + TS2_BLKS, 256>>>(feats1, feats2);               // idx 1
    gemmP_kernel<<<dim3(N2_ / 64, O1_ / 128, B_), 256>>>();                    // idx 2
    fused12_kernel<<<dim3(N1_ / 64, B_), 256, FSM_BYTES>>>(out);               // idx 3 -> ncu
}

// round 12
// speedup vs baseline: 1.1236x; 1.1236x over previous
#include <cuda_runtime.h>
#include <cuda_bf16.h>
#include <cstdint>

// ---- problem constants ----
#define B_    8
#define N1_   8192
#define N2_   2048
#define C1_   128
#define C2_   256
#define INCH  384
#define O1_   256
#define O2_   256

// ---- device scratch ----
__device__ float g_b1eff[O1_], g_b2eff[O2_];
__device__ __align__(16) __nv_bfloat16 g_f1T_hi[(size_t)B_ * N1_ * C1_], g_f1T_lo[(size_t)B_ * N1_ * C1_];
__device__ __align__(16) __nv_bfloat16 g_f2T_hi[(size_t)B_ * N2_ * C2_], g_f2T_lo[(size_t)B_ * N2_ * C2_];
__device__ __align__(16) float g_PT[(size_t)B_ * N2_ * O1_];      // P^T [b][n2][o1]
__device__ int   g_idx[B_ * N1_ * 3];
__device__ float g_wgt[B_ * N1_ * 3];

// fragment-order packed weights (uint4 = 4 mma B-regs per lane)
__device__ __align__(16) uint4 g_W2p_hi [8192], g_W2p_lo [8192];
__device__ __align__(16) uint4 g_W1bp_hi[4096], g_W1bp_lo[4096];
__device__ __align__(16) uint4 g_W1ap_hi[8192], g_W1ap_lo[8192];

// ============================================================
// primitives
// ============================================================
__device__ __forceinline__ uint32_t smem_u32(const void* p) {
    uint32_t a;
    asm("{ .reg .u64 t; cvta.to.shared.u64 t, %1; cvt.u32.u64 %0, t; }" : "=r"(a) : "l"(p));
    return a;
}
__device__ __forceinline__ void ldsm4(uint32_t* r, uint32_t addr) {
    asm volatile("ldmatrix.sync.aligned.m8n8.x4.shared.b16 {%0,%1,%2,%3}, [%4];"
                 : "=r"(r[0]), "=r"(r[1]), "=r"(r[2]), "=r"(r[3]) : "r"(addr));
}
__device__ __forceinline__ void mma16816(float* c, const uint32_t* a, uint32_t b0, uint32_t b1) {
    asm volatile(
        "mma.sync.aligned.m16n8k16.row.col.f32.bf16.bf16.f32 "
        "{%0,%1,%2,%3}, {%4,%5,%6,%7}, {%8,%9}, {%0,%1,%2,%3};"
        : "+f"(c[0]), "+f"(c[1]), "+f"(c[2]), "+f"(c[3])
        : "r"(a[0]), "r"(a[1]), "r"(a[2]), "r"(a[3]), "r"(b0), "r"(b1));
}
__device__ __forceinline__ uint32_t splitpack(float a, float b, uint32_t& lo) {
    __nv_bfloat16 ha = __float2bfloat16(a), hb = __float2bfloat16(b);
    __nv_bfloat16 la = __float2bfloat16(a - __bfloat162float(ha));
    __nv_bfloat16 lb = __float2bfloat16(b - __bfloat162float(hb));
    __nv_bfloat162 H2; H2.x = ha; H2.y = hb;
    __nv_bfloat162 L2; L2.x = la; L2.y = lb;
    lo = *(uint32_t*)&L2;
    return *(uint32_t*)&H2;
}
__device__ __forceinline__ uint32_t fold2(float wa, float wb, float scale, uint32_t& lo) {
    return splitpack(wa * scale, wb * scale, lo);
}

// ============================================================
// FUSED gemm1+gemm2 (byte-identical to the R11-measured 120.8us version)
// ============================================================
#define FSLD 40
#define H1P  264
#define OTP  68
#define OF_H1HI 0
#define OF_H1LO 33792
#define OF_ABUF 67584
#define OF_OUTT 0
#define FSM_BYTES 88064

__global__ void __launch_bounds__(256, 2) fused12_kernel(float* __restrict__ out) {
    extern __shared__ __align__(16) char fsm[];
    __nv_bfloat16* h1hi = (__nv_bfloat16*)(fsm + OF_H1HI);
    __nv_bfloat16* h1lo = (__nv_bfloat16*)(fsm + OF_H1LO);
    float*         outT = (float*)(fsm + OF_OUTT);

    const int tid = threadIdx.x, lane = tid & 31, wid = tid >> 5;
    const int warpM = wid >> 2, warpN = wid & 3;
    const int b = blockIdx.y;
    const int pt0 = blockIdx.x * 64;

    const uint32_t h1hiB = smem_u32(h1hi), h1loB = smem_u32(h1lo);
    const uint32_t abufB = smem_u32(fsm + OF_ABUF);

    const int lrow = tid >> 2;
    const int lcol = (tid & 3) * 8;

    const uint32_t aRowSel = lane & 15;
    const uint32_t aColSel = (lane >> 4) << 3;

    // ---------------- stage 1 ----------------
    const __nv_bfloat16* Ah = g_f1T_hi + ((size_t)b * N1_ + pt0 + lrow) * C1_ + lcol;
    const __nv_bfloat16* Al = g_f1T_lo + ((size_t)b * N1_ + pt0 + lrow) * C1_ + lcol;

    float acc[2][8][4];
    #pragma unroll
    for (int i = 0; i < 2; i++)
        #pragma unroll
        for (int j = 0; j < 8; j++)
            #pragma unroll
            for (int k = 0; k < 4; k++) acc[i][j][k] = 0.f;

    uint4 rA0 = *(const uint4*)Ah;
    uint4 rA1 = *(const uint4*)Al;

    for (int kc = 0; kc < 4; kc++) {
        uint32_t bufO = (kc & 1) * 10240u;
        *(uint4*)(fsm + OF_ABUF + bufO + (lrow * FSLD + lcol) * 2) = rA0;
        *(uint4*)(fsm + OF_ABUF + bufO + 5120 + (lrow * FSLD + lcol) * 2) = rA1;

        int nk = (kc < 3) ? (kc + 1) * 32 : 0;
        rA0 = *(const uint4*)(Ah + nk);
        rA1 = *(const uint4*)(Al + nk);

        __syncthreads();

        #pragma unroll
        for (int ks = 0; ks < 2; ks++) {
            uint4 fh[4], fl[4];
            #pragma unroll
            for (int nj = 0; nj < 4; nj++) {
                size_t o = ((((size_t)kc * 2 + ks) * 4 + warpN) * 4 + nj) * 32 + lane;
                fh[nj] = g_W1bp_hi[o];
                fl[nj] = g_W1bp_lo[o];
            }
            uint32_t ah[2][4], al[2][4];
            #pragma unroll
            for (int mi = 0; mi < 2; mi++) {
                uint32_t off = bufO + ((warpM * 32 + mi * 16 + aRowSel) * FSLD + ks * 16 + aColSel) * 2;
                ldsm4(ah[mi], abufB + off);
                ldsm4(al[mi], abufB + 5120 + off);
            }
            #pragma unroll
            for (int nj = 0; nj < 4; nj++) {
                const uint32_t* BH = (const uint32_t*)&fh[nj];
                const uint32_t* BL = (const uint32_t*)&fl[nj];
                #pragma unroll
                for (int mi = 0; mi < 2; mi++)
                    #pragma unroll
                    for (int sub = 0; sub < 2; sub++) {
                        int ni = nj * 2 + sub;
                        uint32_t b0 = BH[sub * 2], b1 = BH[sub * 2 + 1];
                        uint32_t c0_ = BL[sub * 2], c1_ = BL[sub * 2 + 1];
                        mma16816(acc[mi][ni], ah[mi], b0, b1);
                        mma16816(acc[mi][ni], ah[mi], c0_, c1_);
                        mma16816(acc[mi][ni], al[mi], b0, b1);
                    }
            }
        }
    }
    __syncthreads();

    // ---------------- epilogue 1 ----------------
    {
        const int r0 = lane >> 2;
        const int c0 = (lane & 3) * 2;
        const int*   IX = g_idx + (size_t)b * N1_ * 3;
        const float* WG = g_wgt + (size_t)b * N1_ * 3;
        const float* PT = g_PT + (size_t)b * N2_ * O1_;
        #pragma unroll
        for (int mi = 0; mi < 2; mi++)
            #pragma unroll
            for (int h = 0; h < 2; h++) {
                int gmL = warpM * 32 + mi * 16 + r0 + h * 8;
                int n = pt0 + gmL;
                int i0 = IX[n * 3], i1 = IX[n * 3 + 1], i2 = IX[n * 3 + 2];
                float w0 = WG[n * 3], w1 = WG[n * 3 + 1], w2 = WG[n * 3 + 2];
                #pragma unroll
                for (int ni = 0; ni < 8; ni++) {
                    int gn = warpN * 64 + ni * 8 + c0;
                    float2 p0 = *(const float2*)&PT[(size_t)i0 * O1_ + gn];
                    float2 p1 = *(const float2*)&PT[(size_t)i1 * O1_ + gn];
                    float2 p2 = *(const float2*)&PT[(size_t)i2 * O1_ + gn];
                    float2 bs = *(const float2*)&g_b1eff[gn];
                    float v0 = acc[mi][ni][h * 2 + 0] + bs.x + w0 * p0.x + w1 * p1.x + w2 * p2.x;
                    float v1 = acc[mi][ni][h * 2 + 1] + bs.y + w0 * p0.y + w1 * p1.y + w2 * p2.y;
                    v0 = fmaxf(v0, 0.f); v1 = fmaxf(v1, 0.f);
                    uint32_t lo, hi = splitpack(v0, v1, lo);
                    *(uint32_t*)&h1hi[gmL * H1P + gn] = hi;
                    *(uint32_t*)&h1lo[gmL * H1P + gn] = lo;
                }
            }
    }
    __syncthreads();

    // ---------------- stage 2 (no syncs) ----------------
    float acc2[2][8][4];
    #pragma unroll
    for (int i = 0; i < 2; i++)
        #pragma unroll
        for (int j = 0; j < 8; j++)
            #pragma unroll
            for (int k = 0; k < 4; k++) acc2[i][j][k] = 0.f;

    for (int kc = 0; kc < 8; kc++) {
        #pragma unroll
        for (int ks = 0; ks < 2; ks++) {
            uint4 fh[4], fl[4];
            #pragma unroll
            for (int nj = 0; nj < 4; nj++) {
                size_t o = ((((size_t)kc * 2 + ks) * 4 + warpN) * 4 + nj) * 32 + lane;
                fh[nj] = g_W2p_hi[o];
                fl[nj] = g_W2p_lo[o];
            }
            uint32_t ah[2][4], al[2][4];
            #pragma unroll
            for (int mi = 0; mi < 2; mi++) {
                uint32_t off = ((warpM * 32 + mi * 16 + aRowSel) * H1P + kc * 32 + ks * 16 + aColSel) * 2;
                ldsm4(ah[mi], h1hiB + off);
                ldsm4(al[mi], h1loB + off);
            }
            #pragma unroll
            for (int nj = 0; nj < 4; nj++) {
                const uint32_t* BH = (const uint32_t*)&fh[nj];
                const uint32_t* BL = (const uint32_t*)&fl[nj];
                #pragma unroll
                for (int mi = 0; mi < 2; mi++)
                    #pragma unroll
                    for (int sub = 0; sub < 2; sub++) {
                        int ni = nj * 2 + sub;
                        uint32_t b0 = BH[sub * 2], b1 = BH[sub * 2 + 1];
                        uint32_t c0_ = BL[sub * 2], c1_ = BL[sub * 2 + 1];
                        mma16816(acc2[mi][ni], ah[mi], b0, b1);
                        mma16816(acc2[mi][ni], ah[mi], c0_, c1_);
                        mma16816(acc2[mi][ni], al[mi], b0, b1);
                    }
            }
        }
    }
    __syncthreads();

    // ---------------- epilogue 2 ----------------
    {
        const int r0 = lane >> 2;
        const int c0 = (lane & 3) * 2;
        #pragma unroll
        for (int mi = 0; mi < 2; mi++)
            #pragma unroll
            for (int h = 0; h < 2; h++) {
                int gmL = warpM * 32 + mi * 16 + r0 + h * 8;
                #pragma unroll
                for (int ni = 0; ni < 8; ni++) {
                    int gn = warpN * 64 + ni * 8 + c0;
                    float2 bs = *(const float2*)&g_b2eff[gn];
                    outT[(size_t)gn * OTP + gmL]       = fmaxf(acc2[mi][ni][h * 2 + 0] + bs.x, 0.f);
                    outT[(size_t)(gn + 1) * OTP + gmL] = fmaxf(acc2[mi][ni][h * 2 + 1] + bs.y, 0.f);
                }
            }
    }
    __syncthreads();

    float* dst = out + (size_t)b * O2_ * N1_ + pt0;
    for (int i = tid; i < 256 * 16; i += 256) {
        int o2 = i >> 4;
        int c = (i & 15) << 2;
        uint4 v = *(uint4*)&outT[o2 * OTP + c];
        *(uint4*)(dst + (size_t)o2 * N1_ + c) = v;
    }
}

// ============================================================
// gemmP v2 (unchanged from R11): packed W1a, 1 sync/chunk.
// ============================================================
__global__ void __launch_bounds__(256, 2) gemmP_kernel() {
    __shared__ __align__(16) char gsm[20480];

    const int tid = threadIdx.x, lane = tid & 31, wid = tid >> 5;
    const int warpM = wid >> 2, warpN = wid & 3;
    const int b = blockIdx.z;
    const int Mbase = blockIdx.x * 64;
    const int nb = blockIdx.y;

    float acc[2][4][4];
    #pragma unroll
    for (int i = 0; i < 2; i++)
        #pragma unroll
        for (int j = 0; j < 4; j++)
            #pragma unroll
            for (int k = 0; k < 4; k++) acc[i][j][k] = 0.f;

    const int lrow = tid >> 2;
    const int lcol = (tid & 3) * 8;

    const __nv_bfloat16* pAhi = g_f2T_hi + ((size_t)b * N2_ + Mbase + lrow) * C2_ + lcol;
    const __nv_bfloat16* pAlo = g_f2T_lo + ((size_t)b * N2_ + Mbase + lrow) * C2_ + lcol;

    const uint32_t aRowSel = lane & 15;
    const uint32_t aColSel = (lane >> 4) << 3;
    const uint32_t gsmB = smem_u32(gsm);

    uint4 rA0 = *(const uint4*)pAhi;
    uint4 rA1 = *(const uint4*)pAlo;

    for (int kc = 0; kc < 8; kc++) {
        uint32_t bufO = (kc & 1) * 10240u;
        *(uint4*)(gsm + bufO + (lrow * FSLD + lcol) * 2) = rA0;
        *(uint4*)(gsm + bufO + 5120 + (lrow * FSLD + lcol) * 2) = rA1;

        int nk = (kc < 7) ? (kc + 1) * 32 : 0;
        rA0 = *(const uint4*)(pAhi + nk);
        rA1 = *(const uint4*)(pAlo + nk);

        __syncthreads();

        #pragma unroll
        for (int ks = 0; ks < 2; ks++) {
            uint4 fh[2], fl[2];
            #pragma unroll
            for (int nj = 0; nj < 2; nj++) {
                size_t o = (((((size_t)nb * 8 + kc) * 2 + ks) * 4 + warpN) * 2 + nj) * 32 + lane;
                fh[nj] = g_W1ap_hi[o];
                fl[nj] = g_W1ap_lo[o];
            }
            uint32_t ah[2][4], al[2][4];
            #pragma unroll
            for (int mi = 0; mi < 2; mi++) {
                uint32_t off = bufO + ((warpM * 32 + mi * 16 + aRowSel) * FSLD + ks * 16 + aColSel) * 2;
                ldsm4(ah[mi], gsmB + off);
                ldsm4(al[mi], gsmB + 5120 + off);
            }
            #pragma unroll
            for (int nj = 0; nj < 2; nj++) {
                const uint32_t* BH = (const uint32_t*)&fh[nj];
                const uint32_t* BL = (const uint32_t*)&fl[nj];
                #pragma unroll
                for (int mi = 0; mi < 2; mi++)
                    #pragma unroll
                    for (int sub = 0; sub < 2; sub++) {
                        int ni = nj * 2 + sub;
                        uint32_t b0 = BH[sub * 2], b1 = BH[sub * 2 + 1];
                        uint32_t c0_ = BL[sub * 2], c1_ = BL[sub * 2 + 1];
                        mma16816(acc[mi][ni], ah[mi], b0, b1);
                        mma16816(acc[mi][ni], ah[mi], c0_, c1_);
                        mma16816(acc[mi][ni], al[mi], b0, b1);
                    }
            }
        }
    }

    const int r0 = lane >> 2;
    const int c0 = (lane & 3) * 2;
    float* outP = g_PT + (size_t)b * N2_ * O1_;
    const int Nbase = nb * 128;
    #pragma unroll
    for (int mi = 0; mi < 2; mi++)
        #pragma unroll
        for (int h = 0; h < 2; h++) {
            int gm = Mbase + warpM * 32 + mi * 16 + r0 + h * 8;
            #pragma unroll
            for (int ni = 0; ni < 4; ni++) {
                int gn = Nbase + warpN * 32 + ni * 8 + c0;
                *(float2*)&outP[(size_t)gm * O1_ + gn] =
                    make_float2(acc[mi][ni][h * 2], acc[mi][ni][h * 2 + 1]);
            }
        }
}

// ============================================================
// pack: fold BN + split + fragment-pack all weights (own kernel, no smem)
// ============================================================
#define RS_ 0.99999500003749969f

__global__ void __launch_bounds__(256) pack_kernel(
    const float* __restrict__ W1, const float* __restrict__ b1,
    const float* __restrict__ g1, const float* __restrict__ be1,
    const float* __restrict__ W2, const float* __restrict__ b2,
    const float* __restrict__ g2, const float* __restrict__ be2) {
    int t = blockIdx.x * 256 + threadIdx.x;
    int nt = gridDim.x * 256;

    for (int i = t; i < 8192; i += nt) {
        int lane = i & 31, nj = (i >> 5) & 3, wN = (i >> 7) & 3, ks = (i >> 9) & 1, kc = i >> 10;
        int n0 = wN * 64 + nj * 16, k0 = kc * 32 + ks * 16;
        uint4 h, l;
        uint32_t* hp = (uint32_t*)&h;
        uint32_t* lp = (uint32_t*)&l;
        #pragma unroll
        for (int j = 0; j < 4; j++) {
            int n = n0 + ((j >> 1) << 3) + (lane >> 2);
            int k = k0 + ((j & 1) << 3) + (lane & 3) * 2;
            float s = g2[n] * RS_;
            hp[j] = fold2(W2[(size_t)n * O1_ + k], W2[(size_t)n * O1_ + k + 1], s, lp[j]);
        }
        g_W2p_hi[i] = h;
        g_W2p_lo[i] = l;
    }
    for (int i = t; i < 4096; i += nt) {
        int lane = i & 31, nj = (i >> 5) & 3, wN = (i >> 7) & 3, ks = (i >> 9) & 1, kc = i >> 10;
        int n0 = wN * 64 + nj * 16, k0 = kc * 32 + ks * 16;
        uint4 h, l;
        uint32_t* hp = (uint32_t*)&h;
        uint32_t* lp = (uint32_t*)&l;
        #pragma unroll
        for (int j = 0; j < 4; j++) {
            int n = n0 + ((j >> 1) << 3) + (lane >> 2);
            int k = k0 + ((j & 1) << 3) + (lane & 3) * 2;
            float s = g1[n] * RS_;
            hp[j] = fold2(W1[(size_t)n * INCH + C2_ + k], W1[(size_t)n * INCH + C2_ + k + 1], s, lp[j]);
        }
        g_W1bp_hi[i] = h;
        g_W1bp_lo[i] = l;
    }
    for (int i = t; i < 8192; i += nt) {
        int lane = i & 31, nj = (i >> 5) & 1, wN = (i >> 6) & 3, ks = (i >> 8) & 1,
            kc = (i >> 9) & 7, nb = (i >> 12) & 1;
        int n0 = nb * 128 + wN * 32 + nj * 16, k0 = kc * 32 + ks * 16;
        uint4 h, l;
        uint32_t* hp = (uint32_t*)&h;
        uint32_t* lp = (uint32_t*)&l;
        #pragma unroll
        for (int j = 0; j < 4; j++) {
            int n = n0 + ((j >> 1) << 3) + (lane >> 2);
            int k = k0 + ((j & 1) << 3) + (lane & 3) * 2;
            float s = g1[n] * RS_;
            hp[j] = fold2(W1[(size_t)n * INCH + k], W1[(size_t)n * INCH + k + 1], s, lp[j]);
        }
        g_W1ap_hi[i] = h;
        g_W1ap_lo[i] = l;
    }
    for (int i = t; i < O1_; i += nt) g_b1eff[i] = g1[i] * RS_ * b1[i] + be1[i];
    for (int i = t; i < O2_; i += nt) g_b2eff[i] = g2[i] * RS_ * b2[i] + be2[i];
}

// ============================================================
// kNN: R6/R10-proven (smem float4, 1 point/thread)
// ============================================================
__global__ void __launch_bounds__(256) knn_kernel(const float* __restrict__ xyz1,
                                                  const float* __restrict__ xyz2) {
    __shared__ __align__(16) float4 s2[N2_];
    int b = blockIdx.y;
    const float* q = xyz2 + (size_t)b * N2_ * 3;
    for (int i = threadIdx.x; i < N2_; i += 256) {
        float ax = q[i * 3 + 0], ay = q[i * 3 + 1], az = q[i * 3 + 2];
        s2[i] = make_float4(ax, ay, az, ax * ax + ay * ay + az * az);
    }
    __syncthreads();

    int p = blockIdx.x * 256 + threadIdx.x;
    const float* pp = xyz1 + ((size_t)b * N1_ + p) * 3;
    float x = pp[0], y = pp[1], z = pp[2];
    float p2 = x * x + y * y + z * z;

    float d0 = 3.4e38f, d1 = 3.4e38f, d2 = 3.4e38f;
    int   j0 = 0, j1 = 0, j2 = 0;
    #pragma unroll 4
    for (int m = 0; m < N2_; m++) {
        float4 v = s2[m];
        float dot = x * v.x + y * v.y + z * v.z;
        float dd  = (p2 + v.w) - 2.0f * dot;
        if (dd < d2) {
            if (dd < d1) {
                d2 = d1; j2 = j1;
                if (dd < d0) { d1 = d0; j1 = j0; d0 = dd; j0 = m; }
                else         { d1 = dd; j1 = m; }
            } else { d2 = dd; j2 = m; }
        }
    }
    float r0 = sqrtf(fmaxf(d0, 0.f));
    float r1 = sqrtf(fmaxf(d1, 0.f));
    float r2 = sqrtf(fmaxf(d2, 0.f));
    float w0 = 1.0f / fmaxf(r0, 1e-8f);
    float w1 = 1.0f / fmaxf(r1, 1e-8f);
    float w2 = 1.0f / fmaxf(r2, 1e-8f);
    float inv = 1.0f / (w0 + w1 + w2);

    size_t base = ((size_t)b * N1_ + p) * 3;
    g_idx[base + 0] = j0; g_idx[base + 1] = j1; g_idx[base + 2] = j2;
    g_wgt[base + 0] = w0 * inv; g_wgt[base + 1] = w1 * inv; g_wgt[base + 2] = w2 * inv;
}

// ============================================================
// tsplit: transpose + split feats1 AND feats2 (4.2KB smem)
// ============================================================
#define TS1_BLKS  ((N1_ / 32) * (C1_ / 32) * B_)      // 8192
#define TS2_BLKS  ((N2_ / 32) * (C2_ / 32) * B_)      // 4096

__device__ __forceinline__ void tsplit_tile(int n_t, int c_t, int b,
                                            const float* __restrict__ src,
                                            __nv_bfloat16* __restrict__ dhi,
                                            __nv_bfloat16* __restrict__ dlo,
                                            int C, int Np, float (*t)[33]) {
    int n0 = n_t * 32, c0 = c_t * 32;
    int tx = threadIdx.x & 31, ty = threadIdx.x >> 5;
    #pragma unroll
    for (int r = 0; r < 4; r++) {
        int c = c0 + ty + r * 8;
        t[ty + r * 8][tx] = src[((size_t)b * C + c) * Np + n0 + tx];
    }
    __syncthreads();
    #pragma unroll
    for (int r = 0; r < 4; r++) {
        int n = n0 + ty + r * 8;
        int c = c0 + tx;
        float v = t[tx][ty + r * 8];
        __nv_bfloat16 hi = __float2bfloat16(v);
        size_t o = ((size_t)b * Np + n) * C + c;
        dhi[o] = hi;
        dlo[o] = __float2bfloat16(v - __bfloat162float(hi));
    }
}

__global__ void __launch_bounds__(256) tsplit_kernel(const float* __restrict__ feats1,
                                                     const float* __restrict__ feats2) {
    __shared__ float t[32][33];
    int bid = blockIdx.x;
    if (bid < TS1_BLKS) {
        int n_t = bid & 255, c_t = (bid >> 8) & 3, b = bid >> 10;
        tsplit_tile(n_t, c_t, b, feats1, g_f1T_hi, g_f1T_lo, C1_, N1_, t);
    } else {
        bid -= TS1_BLKS;
        int n_t = bid & 63, c_t = (bid >> 6) & 7, b = bid >> 9;
        tsplit_tile(n_t, c_t, b, feats2, g_f2T_hi, g_f2T_lo, C2_, N2_, t);
    }
}

// ============================================================
extern "C" void kernel_launch(void* const* d_in, const int* in_sizes, int n_in,
                              void* d_out, int out_size) {
    const float* xyz1   = (const float*)d_in[0];
    const float* xyz2   = (const float*)d_in[1];
    const float* feats1 = (const float*)d_in[2];
    const float* feats2 = (const float*)d_in[3];
    const float* W1     = (const float*)d_in[4];
    const float* b1     = (const float*)d_in[5];
    const float* g1     = (const float*)d_in[6];
    const float* be1    = (const float*)d_in[7];
    const float* W2     = (const float*)d_in[8];
    const float* b2     = (const float*)d_in[9];
    const float* g2     = (const float*)d_in[10];
    const float* be2    = (const float*)d_in[11];
    float* out = (float*)d_out;

    cudaFuncSetAttribute(fused12_kernel, cudaFuncAttributeMaxDynamicSharedMemorySize, FSM_BYTES);

    pack_kernel<<<64, 256>>>(W1, b1, g1, be1, W2, b2, g2, be2);       // idx 0
    knn_kernel<<<dim3(N1_ / 256, B_), 256>>>(xyz1, xyz2);             // idx 1
    tsplit_kernel<<<TS1_BLKS + TS2_BLKS, 256>>>(feats1, feats2);      // idx 2
    gemmP_kernel<<<dim3(N2_ / 64, O1_ / 128, B_), 256>>>();           // idx 3 -> ncu
    fused12_kernel<<<dim3(N1_ / 64, B_), 256, FSM_BYTES>>>(out);      // idx 4
}

// round 13
// speedup vs baseline: 1.1514x; 1.0248x over previous
#include <cuda_runtime.h>
#include <cuda_bf16.h>
#include <cstdint>

// ---- problem constants ----
#define B_    8
#define N1_   8192
#define N2_   2048
#define C1_   128
#define C2_   256
#define INCH  384
#define O1_   256
#define O2_   256

// ---- device scratch ----
__device__ float g_b1eff[O1_], g_b2eff[O2_];
__device__ __align__(16) float g_PT[(size_t)B_ * N2_ * O1_];      // P^T [b][n2][o1]
__device__ int   g_idx[B_ * N1_ * 3];
__device__ float g_wgt[B_ * N1_ * 3];

// A operands in mma-fragment order: [b][rowtile][ktile][lane] -> uint4
// f1: rowtile N1/16=512, ktile C1/16=8 ; f2: rowtile N2/16=128, ktile C2/16=16
__device__ __align__(16) uint4 g_f1P_hi[(size_t)B_ * 512 * 8 * 32], g_f1P_lo[(size_t)B_ * 512 * 8 * 32];
__device__ __align__(16) uint4 g_f2P_hi[(size_t)B_ * 128 * 16 * 32], g_f2P_lo[(size_t)B_ * 128 * 16 * 32];

// fragment-order packed weights
__device__ __align__(16) uint4 g_W2p_hi [8192], g_W2p_lo [8192];
__device__ __align__(16) uint4 g_W1bp_hi[4096], g_W1bp_lo[4096];
__device__ __align__(16) uint4 g_W1ap_hi[8192], g_W1ap_lo[8192];

// ============================================================
// primitives
// ============================================================
__device__ __forceinline__ uint32_t smem_u32(const void* p) {
    uint32_t a;
    asm("{ .reg .u64 t; cvta.to.shared.u64 t, %1; cvt.u32.u64 %0, t; }" : "=r"(a) : "l"(p));
    return a;
}
__device__ __forceinline__ void ldsm4(uint32_t* r, uint32_t addr) {
    asm volatile("ldmatrix.sync.aligned.m8n8.x4.shared.b16 {%0,%1,%2,%3}, [%4];"
                 : "=r"(r[0]), "=r"(r[1]), "=r"(r[2]), "=r"(r[3]) : "r"(addr));
}
__device__ __forceinline__ void mma16816(float* c, const uint32_t* a, uint32_t b0, uint32_t b1) {
    asm volatile(
        "mma.sync.aligned.m16n8k16.row.col.f32.bf16.bf16.f32 "
        "{%0,%1,%2,%3}, {%4,%5,%6,%7}, {%8,%9}, {%0,%1,%2,%3};"
        : "+f"(c[0]), "+f"(c[1]), "+f"(c[2]), "+f"(c[3])
        : "r"(a[0]), "r"(a[1]), "r"(a[2]), "r"(a[3]), "r"(b0), "r"(b1));
}
__device__ __forceinline__ uint32_t splitpack(float a, float b, uint32_t& lo) {
    __nv_bfloat16 ha = __float2bfloat16(a), hb = __float2bfloat16(b);
    __nv_bfloat16 la = __float2bfloat16(a - __bfloat162float(ha));
    __nv_bfloat16 lb = __float2bfloat16(b - __bfloat162float(hb));
    __nv_bfloat162 H2; H2.x = ha; H2.y = hb;
    __nv_bfloat162 L2; L2.x = la; L2.y = lb;
    lo = *(uint32_t*)&L2;
    return *(uint32_t*)&H2;
}
__device__ __forceinline__ uint32_t fold2(float wa, float wb, float scale, uint32_t& lo) {
    return splitpack(wa * scale, wb * scale, lo);
}

// ============================================================
// FUSED gemm1+gemm2. Per CTA: 64 points x full O1=256.
// 256 threads = 8 warps (2M x 4N), warp tile 32(M) x 64(N).
// Stage 1: A fragments via LDG.128 from g_f1P (NO smem, NO syncs).
// Stage 2: h1 from smem (ldsm), W2 fragments via LDG (no syncs).
// Only 3 __syncthreads in the whole kernel. smem 69.6KB -> 2 CTAs/SM.
// ============================================================
#define H1P  264
#define OTP  68
#define OF_H1HI 0
#define OF_H1LO 33792
#define OF_OUTT 0
#define FSM_BYTES 69632

__global__ void __launch_bounds__(256, 2) fused12_kernel(float* __restrict__ out) {
    extern __shared__ __align__(16) char fsm[];
    __nv_bfloat16* h1hi = (__nv_bfloat16*)(fsm + OF_H1HI);
    __nv_bfloat16* h1lo = (__nv_bfloat16*)(fsm + OF_H1LO);
    float*         outT = (float*)(fsm + OF_OUTT);

    const int tid = threadIdx.x, lane = tid & 31, wid = tid >> 5;
    const int warpM = wid >> 2, warpN = wid & 3;
    const int b = blockIdx.y;
    const int pt0 = blockIdx.x * 64;

    const uint32_t h1hiB = smem_u32(h1hi), h1loB = smem_u32(h1lo);

    const uint32_t aRowSel = lane & 15;
    const uint32_t aColSel = (lane >> 4) << 3;

    // ---------------- stage 1: h1 = f1 @ W1b^T  (K=128, 8 ktiles, sync-free) ----------------
    float acc[2][8][4];
    #pragma unroll
    for (int i = 0; i < 2; i++)
        #pragma unroll
        for (int j = 0; j < 8; j++)
            #pragma unroll
            for (int k = 0; k < 4; k++) acc[i][j][k] = 0.f;

    const size_t aB1 = (((size_t)b * 512 + blockIdx.x * 4 + warpM * 2) * 8) * 32 + lane; // mi stride 256

    for (int kt = 0; kt < 8; kt++) {
        uint4 afh[2], afl[2];
        #pragma unroll
        for (int mi = 0; mi < 2; mi++) {
            afh[mi] = g_f1P_hi[aB1 + mi * 256 + kt * 32];
            afl[mi] = g_f1P_lo[aB1 + mi * 256 + kt * 32];
        }
        uint4 fh[4], fl[4];
        #pragma unroll
        for (int nj = 0; nj < 4; nj++) {
            size_t o = (((size_t)kt * 4 + warpN) * 4 + nj) * 32 + lane;
            fh[nj] = g_W1bp_hi[o];
            fl[nj] = g_W1bp_lo[o];
        }
        #pragma unroll
        for (int nj = 0; nj < 4; nj++) {
            const uint32_t* BH = (const uint32_t*)&fh[nj];
            const uint32_t* BL = (const uint32_t*)&fl[nj];
            #pragma unroll
            for (int mi = 0; mi < 2; mi++) {
                const uint32_t* AH = (const uint32_t*)&afh[mi];
                const uint32_t* AL = (const uint32_t*)&afl[mi];
                #pragma unroll
                for (int sub = 0; sub < 2; sub++) {
                    int ni = nj * 2 + sub;
                    uint32_t b0 = BH[sub * 2], b1 = BH[sub * 2 + 1];
                    uint32_t c0_ = BL[sub * 2], c1_ = BL[sub * 2 + 1];
                    mma16816(acc[mi][ni], AH, b0, b1);
                    mma16816(acc[mi][ni], AH, c0_, c1_);
                    mma16816(acc[mi][ni], AL, b0, b1);
                }
            }
        }
    }

    // ---------------- epilogue 1: gather + bias + relu -> h1 smem ----------------
    {
        const int r0 = lane >> 2;
        const int c0 = (lane & 3) * 2;
        const int*   IX = g_idx + (size_t)b * N1_ * 3;
        const float* WG = g_wgt + (size_t)b * N1_ * 3;
        const float* PT = g_PT + (size_t)b * N2_ * O1_;
        #pragma unroll
        for (int mi = 0; mi < 2; mi++)
            #pragma unroll
            for (int h = 0; h < 2; h++) {
                int gmL = warpM * 32 + mi * 16 + r0 + h * 8;
                int n = pt0 + gmL;
                int i0 = IX[n * 3], i1 = IX[n * 3 + 1], i2 = IX[n * 3 + 2];
                float w0 = WG[n * 3], w1 = WG[n * 3 + 1], w2 = WG[n * 3 + 2];
                #pragma unroll
                for (int ni = 0; ni < 8; ni++) {
                    int gn = warpN * 64 + ni * 8 + c0;
                    float2 p0 = *(const float2*)&PT[(size_t)i0 * O1_ + gn];
                    float2 p1 = *(const float2*)&PT[(size_t)i1 * O1_ + gn];
                    float2 p2 = *(const float2*)&PT[(size_t)i2 * O1_ + gn];
                    float2 bs = *(const float2*)&g_b1eff[gn];
                    float v0 = acc[mi][ni][h * 2 + 0] + bs.x + w0 * p0.x + w1 * p1.x + w2 * p2.x;
                    float v1 = acc[mi][ni][h * 2 + 1] + bs.y + w0 * p0.y + w1 * p1.y + w2 * p2.y;
                    v0 = fmaxf(v0, 0.f); v1 = fmaxf(v1, 0.f);
                    uint32_t lo, hi = splitpack(v0, v1, lo);
                    *(uint32_t*)&h1hi[gmL * H1P + gn] = hi;
                    *(uint32_t*)&h1lo[gmL * H1P + gn] = lo;
                }
            }
    }
    __syncthreads();   // h1 complete & visible

    // ---------------- stage 2: out = relu(h1 @ W2^T + b2)  (K=256, no syncs) ----------------
    float acc2[2][8][4];
    #pragma unroll
    for (int i = 0; i < 2; i++)
        #pragma unroll
        for (int j = 0; j < 8; j++)
            #pragma unroll
            for (int k = 0; k < 4; k++) acc2[i][j][k] = 0.f;

    for (int kc = 0; kc < 8; kc++) {
        #pragma unroll
        for (int ks = 0; ks < 2; ks++) {
            uint4 fh[4], fl[4];
            #pragma unroll
            for (int nj = 0; nj < 4; nj++) {
                size_t o = ((((size_t)kc * 2 + ks) * 4 + warpN) * 4 + nj) * 32 + lane;
                fh[nj] = g_W2p_hi[o];
                fl[nj] = g_W2p_lo[o];
            }
            uint32_t ah[2][4], al[2][4];
            #pragma unroll
            for (int mi = 0; mi < 2; mi++) {
                uint32_t off = ((warpM * 32 + mi * 16 + aRowSel) * H1P + kc * 32 + ks * 16 + aColSel) * 2;
                ldsm4(ah[mi], h1hiB + off);
                ldsm4(al[mi], h1loB + off);
            }
            #pragma unroll
            for (int nj = 0; nj < 4; nj++) {
                const uint32_t* BH = (const uint32_t*)&fh[nj];
                const uint32_t* BL = (const uint32_t*)&fl[nj];
                #pragma unroll
                for (int mi = 0; mi < 2; mi++)
                    #pragma unroll
                    for (int sub = 0; sub < 2; sub++) {
                        int ni = nj * 2 + sub;
                        uint32_t b0 = BH[sub * 2], b1 = BH[sub * 2 + 1];
                        uint32_t c0_ = BL[sub * 2], c1_ = BL[sub * 2 + 1];
                        mma16816(acc2[mi][ni], ah[mi], b0, b1);
                        mma16816(acc2[mi][ni], ah[mi], c0_, c1_);
                        mma16816(acc2[mi][ni], al[mi], b0, b1);
                    }
            }
        }
    }
    __syncthreads();   // all h1 reads done before outT overwrites it

    // ---------------- epilogue 2: transpose via smem, coalesced store ----------------
    {
        const int r0 = lane >> 2;
        const int c0 = (lane & 3) * 2;
        #pragma unroll
        for (int mi = 0; mi < 2; mi++)
            #pragma unroll
            for (int h = 0; h < 2; h++) {
                int gmL = warpM * 32 + mi * 16 + r0 + h * 8;
                #pragma unroll
                for (int ni = 0; ni < 8; ni++) {
                    int gn = warpN * 64 + ni * 8 + c0;
                    float2 bs = *(const float2*)&g_b2eff[gn];
                    outT[(size_t)gn * OTP + gmL]       = fmaxf(acc2[mi][ni][h * 2 + 0] + bs.x, 0.f);
                    outT[(size_t)(gn + 1) * OTP + gmL] = fmaxf(acc2[mi][ni][h * 2 + 1] + bs.y, 0.f);
                }
            }
    }
    __syncthreads();

    float* dst = out + (size_t)b * O2_ * N1_ + pt0;
    for (int i = tid; i < 256 * 16; i += 256) {
        int o2 = i >> 4;
        int c = (i & 15) << 2;
        uint4 v = *(uint4*)&outT[o2 * OTP + c];
        *(uint4*)(dst + (size_t)o2 * N1_ + c) = v;
    }
}

// ============================================================
// gemmP v3: PT = f2 @ W1a^T — ALL operands fragment-packed.
// Zero smem, zero syncthreads, pure LDG + MMA.
// M=64 (n2), N=128 (o1, nb), K=256 (16 ktiles).
// ============================================================
__global__ void __launch_bounds__(256, 2) gemmP_kernel() {
    const int tid = threadIdx.x, lane = tid & 31, wid = tid >> 5;
    const int warpM = wid >> 2, warpN = wid & 3;
    const int b = blockIdx.z;
    const int Mbase = blockIdx.x * 64;
    const int nb = blockIdx.y;

    float acc[2][4][4];
    #pragma unroll
    for (int i = 0; i < 2; i++)
        #pragma unroll
        for (int j = 0; j < 4; j++)
            #pragma unroll
            for (int k = 0; k < 4; k++) acc[i][j][k] = 0.f;

    const size_t aB = (((size_t)b * 128 + (Mbase >> 4) + warpM * 2) * 16) * 32 + lane;  // mi stride 512

    for (int kt = 0; kt < 16; kt++) {
        uint4 afh[2], afl[2];
        #pragma unroll
        for (int mi = 0; mi < 2; mi++) {
            afh[mi] = g_f2P_hi[aB + mi * 512 + kt * 32];
            afl[mi] = g_f2P_lo[aB + mi * 512 + kt * 32];
        }
        uint4 fh[2], fl[2];
        #pragma unroll
        for (int nj = 0; nj < 2; nj++) {
            size_t o = (((size_t)(nb * 16 + kt) * 4 + warpN) * 2 + nj) * 32 + lane;
            fh[nj] = g_W1ap_hi[o];
            fl[nj] = g_W1ap_lo[o];
        }
        #pragma unroll
        for (int nj = 0; nj < 2; nj++) {
            const uint32_t* BH = (const uint32_t*)&fh[nj];
            const uint32_t* BL = (const uint32_t*)&fl[nj];
            #pragma unroll
            for (int mi = 0; mi < 2; mi++) {
                const uint32_t* AH = (const uint32_t*)&afh[mi];
                const uint32_t* AL = (const uint32_t*)&afl[mi];
                #pragma unroll
                for (int sub = 0; sub < 2; sub++) {
                    int ni = nj * 2 + sub;
                    uint32_t b0 = BH[sub * 2], b1 = BH[sub * 2 + 1];
                    uint32_t c0_ = BL[sub * 2], c1_ = BL[sub * 2 + 1];
                    mma16816(acc[mi][ni], AH, b0, b1);
                    mma16816(acc[mi][ni], AH, c0_, c1_);
                    mma16816(acc[mi][ni], AL, b0, b1);
                }
            }
        }
    }

    const int r0 = lane >> 2;
    const int c0 = (lane & 3) * 2;
    float* outP = g_PT + (size_t)b * N2_ * O1_;
    const int Nbase = nb * 128;
    #pragma unroll
    for (int mi = 0; mi < 2; mi++)
        #pragma unroll
        for (int h = 0; h < 2; h++) {
            int gm = Mbase + warpM * 32 + mi * 16 + r0 + h * 8;
            #pragma unroll
            for (int ni = 0; ni < 4; ni++) {
                int gn = Nbase + warpN * 32 + ni * 8 + c0;
                *(float2*)&outP[(size_t)gm * O1_ + gn] =
                    make_float2(acc[mi][ni][h * 2], acc[mi][ni][h * 2 + 1]);
            }
        }
}

// ============================================================
// prepsplit: ONE kernel. First TS1+TS2 blocks: transpose feats and emit
// A-fragment-packed hi/lo. Last PACK_BLKS: fold+split+pack weights + biases.
// smem only 4.2KB -> high occupancy everywhere.
// ============================================================
#define TS1_BLKS  ((N1_ / 32) * (C1_ / 32) * B_)      // 8192
#define TS2_BLKS  ((N2_ / 32) * (C2_ / 32) * B_)      // 4096
#define PACK_BLKS 64
#define RS_ 0.99999500003749969f

// phase 2 of tsplit: write 4 fragment tiles (16x16) from the 32x32 transposed tile
__device__ __forceinline__ void tsplit_pack(int n_t, int c_t, int b,
                                            const float* __restrict__ src,
                                            uint4* __restrict__ phi, uint4* __restrict__ plo,
                                            int C, int Np, float (*t)[33]) {
    int n0 = n_t * 32, c0 = c_t * 32;
    int tx = threadIdx.x & 31, ty = threadIdx.x >> 5;
    #pragma unroll
    for (int r = 0; r < 4; r++) {
        int c = c0 + ty + r * 8;
        t[ty + r * 8][tx] = src[((size_t)b * C + c) * Np + n0 + tx];
    }
    __syncthreads();
    int i = threadIdx.x;
    if (i < 128) {
        int tile = i >> 5, lane = i & 31;
        int tn = tile & 1, tc = tile >> 1;
        uint4 h, l;
        uint32_t* hp = (uint32_t*)&h;
        uint32_t* lp = (uint32_t*)&l;
        #pragma unroll
        for (int j = 0; j < 4; j++) {
            int nl = tn * 16 + ((j & 1) << 3) + (lane >> 2);       // m within tile
            int cl = tc * 16 + ((j >> 1) << 3) + (lane & 3) * 2;   // k within tile
            hp[j] = splitpack(t[cl][nl], t[cl + 1][nl], lp[j]);
        }
        int NT = Np / 16, KT = C / 16;
        int rt = n_t * 2 + tn, kt = c_t * 2 + tc;
        size_t o = (((size_t)b * NT + rt) * KT + kt) * 32 + lane;
        phi[o] = h;
        plo[o] = l;
    }
}

__global__ void __launch_bounds__(256) prepsplit_kernel(
    const float* __restrict__ feats1, const float* __restrict__ feats2,
    const float* __restrict__ W1, const float* __restrict__ b1,
    const float* __restrict__ g1, const float* __restrict__ be1,
    const float* __restrict__ W2, const float* __restrict__ b2,
    const float* __restrict__ g2, const float* __restrict__ be2) {
    __shared__ float t[32][33];
    int bid = blockIdx.x;
    if (bid < TS1_BLKS) {
        int n_t = bid & 255, c_t = (bid >> 8) & 3, b = bid >> 10;
        tsplit_pack(n_t, c_t, b, feats1, g_f1P_hi, g_f1P_lo, C1_, N1_, t);
        return;
    }
    bid -= TS1_BLKS;
    if (bid < TS2_BLKS) {
        int n_t = bid & 63, c_t = (bid >> 6) & 7, b = bid >> 9;
        tsplit_pack(n_t, c_t, b, feats2, g_f2P_hi, g_f2P_lo, C2_, N2_, t);
        return;
    }
    bid -= TS2_BLKS;
    // ---- weight pack ----
    int tt = bid * 256 + threadIdx.x;
    int nt = PACK_BLKS * 256;
    for (int i = tt; i < 8192; i += nt) {
        int lane = i & 31, nj = (i >> 5) & 3, wN = (i >> 7) & 3, ks = (i >> 9) & 1, kc = i >> 10;
        int n0 = wN * 64 + nj * 16, k0 = kc * 32 + ks * 16;
        uint4 h, l;
        uint32_t* hp = (uint32_t*)&h;
        uint32_t* lp = (uint32_t*)&l;
        #pragma unroll
        for (int j = 0; j < 4; j++) {
            int n = n0 + ((j >> 1) << 3) + (lane >> 2);
            int k = k0 + ((j & 1) << 3) + (lane & 3) * 2;
            float s = g2[n] * RS_;
            hp[j] = fold2(W2[(size_t)n * O1_ + k], W2[(size_t)n * O1_ + k + 1], s, lp[j]);
        }
        g_W2p_hi[i] = h;
        g_W2p_lo[i] = l;
    }
    for (int i = tt; i < 4096; i += nt) {
        int lane = i & 31, nj = (i >> 5) & 3, wN = (i >> 7) & 3, ks = (i >> 9) & 1, kc = i >> 10;
        int n0 = wN * 64 + nj * 16, k0 = kc * 32 + ks * 16;
        uint4 h, l;
        uint32_t* hp = (uint32_t*)&h;
        uint32_t* lp = (uint32_t*)&l;
        #pragma unroll
        for (int j = 0; j < 4; j++) {
            int n = n0 + ((j >> 1) << 3) + (lane >> 2);
            int k = k0 + ((j & 1) << 3) + (lane & 3) * 2;
            float s = g1[n] * RS_;
            hp[j] = fold2(W1[(size_t)n * INCH + C2_ + k], W1[(size_t)n * INCH + C2_ + k + 1], s, lp[j]);
        }
        g_W1bp_hi[i] = h;
        g_W1bp_lo[i] = l;
    }
    for (int i = tt; i < 8192; i += nt) {
        int lane = i & 31, nj = (i >> 5) & 1, wN = (i >> 6) & 3, ks = (i >> 8) & 1,
            kc = (i >> 9) & 7, nb = (i >> 12) & 1;
        int n0 = nb * 128 + wN * 32 + nj * 16, k0 = kc * 32 + ks * 16;
        uint4 h, l;
        uint32_t* hp = (uint32_t*)&h;
        uint32_t* lp = (uint32_t*)&l;
        #pragma unroll
        for (int j = 0; j < 4; j++) {
            int n = n0 + ((j >> 1) << 3) + (lane >> 2);
            int k = k0 + ((j & 1) << 3) + (lane & 3) * 2;
            float s = g1[n] * RS_;
            hp[j] = fold2(W1[(size_t)n * INCH + k], W1[(size_t)n * INCH + k + 1], s, lp[j]);
        }
        g_W1ap_hi[i] = h;
        g_W1ap_lo[i] = l;
    }
    for (int i = tt; i < O1_; i += nt) g_b1eff[i] = g1[i] * RS_ * b1[i] + be1[i];
    for (int i = tt; i < O2_; i += nt) g_b2eff[i] = g2[i] * RS_ * b2[i] + be2[i];
}

// ============================================================
// kNN: R6/R10-proven (smem float4, 1 point/thread)
// ============================================================
__global__ void __launch_bounds__(256) knn_kernel(const float* __restrict__ xyz1,
                                                  const float* __restrict__ xyz2) {
    __shared__ __align__(16) float4 s2[N2_];
    int b = blockIdx.y;
    const float* q = xyz2 + (size_t)b * N2_ * 3;
    for (int i = threadIdx.x; i < N2_; i += 256) {
        float ax = q[i * 3 + 0], ay = q[i * 3 + 1], az = q[i * 3 + 2];
        s2[i] = make_float4(ax, ay, az, ax * ax + ay * ay + az * az);
    }
    __syncthreads();

    int p = blockIdx.x * 256 + threadIdx.x;
    const float* pp = xyz1 + ((size_t)b * N1_ + p) * 3;
    float x = pp[0], y = pp[1], z = pp[2];
    float p2 = x * x + y * y + z * z;

    float d0 = 3.4e38f, d1 = 3.4e38f, d2 = 3.4e38f;
    int   j0 = 0, j1 = 0, j2 = 0;
    #pragma unroll 4
    for (int m = 0; m < N2_; m++) {
        float4 v = s2[m];
        float dot = x * v.x + y * v.y + z * v.z;
        float dd  = (p2 + v.w) - 2.0f * dot;
        if (dd < d2) {
            if (dd < d1) {
                d2 = d1; j2 = j1;
                if (dd < d0) { d1 = d0; j1 = j0; d0 = dd; j0 = m; }
                else         { d1 = dd; j1 = m; }
            } else { d2 = dd; j2 = m; }
        }
    }
    float r0 = sqrtf(fmaxf(d0, 0.f));
    float r1 = sqrtf(fmaxf(d1, 0.f));
    float r2 = sqrtf(fmaxf(d2, 0.f));
    float w0 = 1.0f / fmaxf(r0, 1e-8f);
    float w1 = 1.0f / fmaxf(r1, 1e-8f);
    float w2 = 1.0f / fmaxf(r2, 1e-8f);
    float inv = 1.0f / (w0 + w1 + w2);

    size_t base = ((size_t)b * N1_ + p) * 3;
    g_idx[base + 0] = j0; g_idx[base + 1] = j1; g_idx[base + 2] = j2;
    g_wgt[base + 0] = w0 * inv; g_wgt[base + 1] = w1 * inv; g_wgt[base + 2] = w2 * inv;
}

// ============================================================
extern "C" void kernel_launch(void* const* d_in, const int* in_sizes, int n_in,
                              void* d_out, int out_size) {
    const float* xyz1   = (const float*)d_in[0];
    const float* xyz2   = (const float*)d_in[1];
    const float* feats1 = (const float*)d_in[2];
    const float* feats2 = (const float*)d_in[3];
    const float* W1     = (const float*)d_in[4];
    const float* b1     = (const float*)d_in[5];
    const float* g1     = (const float*)d_in[6];
    const float* be1    = (const float*)d_in[7];
    const float* W2     = (const float*)d_in[8];
    const float* b2     = (const float*)d_in[9];
    const float* g2     = (const float*)d_in[10];
    const float* be2    = (const float*)d_in[11];
    float* out = (float*)d_out;

    cudaFuncSetAttribute(fused12_kernel, cudaFuncAttributeMaxDynamicSharedMemorySize, FSM_BYTES);

    prepsplit_kernel<<<TS1_BLKS + TS2_BLKS + PACK_BLKS, 256>>>(
        feats1, feats2, W1, b1, g1, be1, W2, b2, g2, be2);            // idx 0
    knn_kernel<<<dim3(N1_ / 256, B_), 256>>>(xyz1, xyz2);             // idx 1
    gemmP_kernel<<<dim3(N2_ / 64, O1_ / 128, B_), 256>>>();           // idx 2
    fused12_kernel<<<dim3(N1_ / 64, B_), 256, FSM_BYTES>>>(out);      // idx 3 -> ncu
}

// round 14
// speedup vs baseline: 1.2219x; 1.0612x over previous
#include <cuda_runtime.h>
#include <cuda_bf16.h>
#include <cstdint>

// ---- problem constants ----
#define B_    8
#define N1_   8192
#define N2_   2048
#define C1_   128
#define C2_   256
#define INCH  384
#define O1_   256
#define O2_   256

// ---- device scratch ----
__device__ float g_b1eff[O1_], g_b2eff[O2_];
__device__ __align__(16) float g_PT[(size_t)B_ * N2_ * O1_];      // P^T [b][n2][o1]
__device__ int   g_idx[B_ * N1_ * 3];
__device__ float g_wgt[B_ * N1_ * 3];

// A operands in mma-fragment order: [b][rowtile][ktile][lane] -> uint4
__device__ __align__(16) uint4 g_f1P_hi[(size_t)B_ * 512 * 8 * 32], g_f1P_lo[(size_t)B_ * 512 * 8 * 32];
__device__ __align__(16) uint4 g_f2P_hi[(size_t)B_ * 128 * 16 * 32], g_f2P_lo[(size_t)B_ * 128 * 16 * 32];

// fragment-order packed weights
__device__ __align__(16) uint4 g_W2p_hi [8192], g_W2p_lo [8192];
__device__ __align__(16) uint4 g_W1bp_hi[4096], g_W1bp_lo[4096];
__device__ __align__(16) uint4 g_W1ap_hi[8192], g_W1ap_lo[8192];

// ============================================================
// primitives
// ============================================================
__device__ __forceinline__ uint32_t smem_u32(const void* p) {
    uint32_t a;
    asm("{ .reg .u64 t; cvta.to.shared.u64 t, %1; cvt.u32.u64 %0, t; }" : "=r"(a) : "l"(p));
    return a;
}
__device__ __forceinline__ void ldsm4(uint32_t* r, uint32_t addr) {
    asm volatile("ldmatrix.sync.aligned.m8n8.x4.shared.b16 {%0,%1,%2,%3}, [%4];"
                 : "=r"(r[0]), "=r"(r[1]), "=r"(r[2]), "=r"(r[3]) : "r"(addr));
}
__device__ __forceinline__ void mma16816(float* c, const uint32_t* a, uint32_t b0, uint32_t b1) {
    asm volatile(
        "mma.sync.aligned.m16n8k16.row.col.f32.bf16.bf16.f32 "
        "{%0,%1,%2,%3}, {%4,%5,%6,%7}, {%8,%9}, {%0,%1,%2,%3};"
        : "+f"(c[0]), "+f"(c[1]), "+f"(c[2]), "+f"(c[3])
        : "r"(a[0]), "r"(a[1]), "r"(a[2]), "r"(a[3]), "r"(b0), "r"(b1));
}
__device__ __forceinline__ uint32_t splitpack(float a, float b, uint32_t& lo) {
    __nv_bfloat16 ha = __float2bfloat16(a), hb = __float2bfloat16(b);
    __nv_bfloat16 la = __float2bfloat16(a - __bfloat162float(ha));
    __nv_bfloat16 lb = __float2bfloat16(b - __bfloat162float(hb));
    __nv_bfloat162 H2; H2.x = ha; H2.y = hb;
    __nv_bfloat162 L2; L2.x = la; L2.y = lb;
    lo = *(uint32_t*)&L2;
    return *(uint32_t*)&H2;
}
__device__ __forceinline__ uint32_t fold2(float wa, float wb, float scale, uint32_t& lo) {
    return splitpack(wa * scale, wb * scale, lo);
}

// ============================================================
// FUSED gemm1+gemm2 (byte-identical to the R13-measured 117.8us version)
// ============================================================
#define H1P  264
#define OTP  68
#define OF_H1HI 0
#define OF_H1LO 33792
#define OF_OUTT 0
#define FSM_BYTES 69632

__global__ void __launch_bounds__(256, 2) fused12_kernel(float* __restrict__ out) {
    extern __shared__ __align__(16) char fsm[];
    __nv_bfloat16* h1hi = (__nv_bfloat16*)(fsm + OF_H1HI);
    __nv_bfloat16* h1lo = (__nv_bfloat16*)(fsm + OF_H1LO);
    float*         outT = (float*)(fsm + OF_OUTT);

    const int tid = threadIdx.x, lane = tid & 31, wid = tid >> 5;
    const int warpM = wid >> 2, warpN = wid & 3;
    const int b = blockIdx.y;
    const int pt0 = blockIdx.x * 64;

    const uint32_t h1hiB = smem_u32(h1hi), h1loB = smem_u32(h1lo);

    const uint32_t aRowSel = lane & 15;
    const uint32_t aColSel = (lane >> 4) << 3;

    // ---------------- stage 1: sync-free, A fragments from g_f1P ----------------
    float acc[2][8][4];
    #pragma unroll
    for (int i = 0; i < 2; i++)
        #pragma unroll
        for (int j = 0; j < 8; j++)
            #pragma unroll
            for (int k = 0; k < 4; k++) acc[i][j][k] = 0.f;

    const size_t aB1 = (((size_t)b * 512 + blockIdx.x * 4 + warpM * 2) * 8) * 32 + lane;

    for (int kt = 0; kt < 8; kt++) {
        uint4 afh[2], afl[2];
        #pragma unroll
        for (int mi = 0; mi < 2; mi++) {
            afh[mi] = g_f1P_hi[aB1 + mi * 256 + kt * 32];
            afl[mi] = g_f1P_lo[aB1 + mi * 256 + kt * 32];
        }
        uint4 fh[4], fl[4];
        #pragma unroll
        for (int nj = 0; nj < 4; nj++) {
            size_t o = (((size_t)kt * 4 + warpN) * 4 + nj) * 32 + lane;
            fh[nj] = g_W1bp_hi[o];
            fl[nj] = g_W1bp_lo[o];
        }
        #pragma unroll
        for (int nj = 0; nj < 4; nj++) {
            const uint32_t* BH = (const uint32_t*)&fh[nj];
            const uint32_t* BL = (const uint32_t*)&fl[nj];
            #pragma unroll
            for (int mi = 0; mi < 2; mi++) {
                const uint32_t* AH = (const uint32_t*)&afh[mi];
                const uint32_t* AL = (const uint32_t*)&afl[mi];
                #pragma unroll
                for (int sub = 0; sub < 2; sub++) {
                    int ni = nj * 2 + sub;
                    uint32_t b0 = BH[sub * 2], b1 = BH[sub * 2 + 1];
                    uint32_t c0_ = BL[sub * 2], c1_ = BL[sub * 2 + 1];
                    mma16816(acc[mi][ni], AH, b0, b1);
                    mma16816(acc[mi][ni], AH, c0_, c1_);
                    mma16816(acc[mi][ni], AL, b0, b1);
                }
            }
        }
    }

    // ---------------- epilogue 1: gather + bias + relu -> h1 smem ----------------
    {
        const int r0 = lane >> 2;
        const int c0 = (lane & 3) * 2;
        const int*   IX = g_idx + (size_t)b * N1_ * 3;
        const float* WG = g_wgt + (size_t)b * N1_ * 3;
        const float* PT = g_PT + (size_t)b * N2_ * O1_;
        #pragma unroll
        for (int mi = 0; mi < 2; mi++)
            #pragma unroll
            for (int h = 0; h < 2; h++) {
                int gmL = warpM * 32 + mi * 16 + r0 + h * 8;
                int n = pt0 + gmL;
                int i0 = IX[n * 3], i1 = IX[n * 3 + 1], i2 = IX[n * 3 + 2];
                float w0 = WG[n * 3], w1 = WG[n * 3 + 1], w2 = WG[n * 3 + 2];
                #pragma unroll
                for (int ni = 0; ni < 8; ni++) {
                    int gn = warpN * 64 + ni * 8 + c0;
                    float2 p0 = *(const float2*)&PT[(size_t)i0 * O1_ + gn];
                    float2 p1 = *(const float2*)&PT[(size_t)i1 * O1_ + gn];
                    float2 p2 = *(const float2*)&PT[(size_t)i2 * O1_ + gn];
                    float2 bs = *(const float2*)&g_b1eff[gn];
                    float v0 = acc[mi][ni][h * 2 + 0] + bs.x + w0 * p0.x + w1 * p1.x + w2 * p2.x;
                    float v1 = acc[mi][ni][h * 2 + 1] + bs.y + w0 * p0.y + w1 * p1.y + w2 * p2.y;
                    v0 = fmaxf(v0, 0.f); v1 = fmaxf(v1, 0.f);
                    uint32_t lo, hi = splitpack(v0, v1, lo);
                    *(uint32_t*)&h1hi[gmL * H1P + gn] = hi;
                    *(uint32_t*)&h1lo[gmL * H1P + gn] = lo;
                }
            }
    }
    __syncthreads();

    // ---------------- stage 2: no syncs ----------------
    float acc2[2][8][4];
    #pragma unroll
    for (int i = 0; i < 2; i++)
        #pragma unroll
        for (int j = 0; j < 8; j++)
            #pragma unroll
            for (int k = 0; k < 4; k++) acc2[i][j][k] = 0.f;

    for (int kc = 0; kc < 8; kc++) {
        #pragma unroll
        for (int ks = 0; ks < 2; ks++) {
            uint4 fh[4], fl[4];
            #pragma unroll
            for (int nj = 0; nj < 4; nj++) {
                size_t o = ((((size_t)kc * 2 + ks) * 4 + warpN) * 4 + nj) * 32 + lane;
                fh[nj] = g_W2p_hi[o];
                fl[nj] = g_W2p_lo[o];
            }
            uint32_t ah[2][4], al[2][4];
            #pragma unroll
            for (int mi = 0; mi < 2; mi++) {
                uint32_t off = ((warpM * 32 + mi * 16 + aRowSel) * H1P + kc * 32 + ks * 16 + aColSel) * 2;
                ldsm4(ah[mi], h1hiB + off);
                ldsm4(al[mi], h1loB + off);
            }
            #pragma unroll
            for (int nj = 0; nj < 4; nj++) {
                const uint32_t* BH = (const uint32_t*)&fh[nj];
                const uint32_t* BL = (const uint32_t*)&fl[nj];
                #pragma unroll
                for (int mi = 0; mi < 2; mi++)
                    #pragma unroll
                    for (int sub = 0; sub < 2; sub++) {
                        int ni = nj * 2 + sub;
                        uint32_t b0 = BH[sub * 2], b1 = BH[sub * 2 + 1];
                        uint32_t c0_ = BL[sub * 2], c1_ = BL[sub * 2 + 1];
                        mma16816(acc2[mi][ni], ah[mi], b0, b1);
                        mma16816(acc2[mi][ni], ah[mi], c0_, c1_);
                        mma16816(acc2[mi][ni], al[mi], b0, b1);
                    }
            }
        }
    }
    __syncthreads();

    // ---------------- epilogue 2 ----------------
    {
        const int r0 = lane >> 2;
        const int c0 = (lane & 3) * 2;
        #pragma unroll
        for (int mi = 0; mi < 2; mi++)
            #pragma unroll
            for (int h = 0; h < 2; h++) {
                int gmL = warpM * 32 + mi * 16 + r0 + h * 8;
                #pragma unroll
                for (int ni = 0; ni < 8; ni++) {
                    int gn = warpN * 64 + ni * 8 + c0;
                    float2 bs = *(const float2*)&g_b2eff[gn];
                    outT[(size_t)gn * OTP + gmL]       = fmaxf(acc2[mi][ni][h * 2 + 0] + bs.x, 0.f);
                    outT[(size_t)(gn + 1) * OTP + gmL] = fmaxf(acc2[mi][ni][h * 2 + 1] + bs.y, 0.f);
                }
            }
    }
    __syncthreads();

    float* dst = out + (size_t)b * O2_ * N1_ + pt0;
    for (int i = tid; i < 256 * 16; i += 256) {
        int o2 = i >> 4;
        int c = (i & 15) << 2;
        uint4 v = *(uint4*)&outT[o2 * OTP + c];
        *(uint4*)(dst + (size_t)o2 * N1_ + c) = v;
    }
}

// ============================================================
// MERGED knn + gemmP kernel (independent work, overlapped).
// blocks [0, 256):   kNN (smem float4 cache, 1 pt/thread)
// blocks [256, 768): gemmP v3 (zero smem, zero syncs, packed operands)
// ============================================================
#define KNN_BLKS 256   // (N1/256) * B

__global__ void __launch_bounds__(256, 2) knngemmP_kernel(const float* __restrict__ xyz1,
                                                          const float* __restrict__ xyz2) {
    __shared__ __align__(16) float4 s2[N2_];   // used only by knn blocks

    if (blockIdx.x < KNN_BLKS) {
        // ---------------- kNN (R6/R10-proven body) ----------------
        int px = blockIdx.x & 31, b = blockIdx.x >> 5;
        const float* q = xyz2 + (size_t)b * N2_ * 3;
        for (int i = threadIdx.x; i < N2_; i += 256) {
            float ax = q[i * 3 + 0], ay = q[i * 3 + 1], az = q[i * 3 + 2];
            s2[i] = make_float4(ax, ay, az, ax * ax + ay * ay + az * az);
        }
        __syncthreads();

        int p = px * 256 + threadIdx.x;
        const float* pp = xyz1 + ((size_t)b * N1_ + p) * 3;
        float x = pp[0], y = pp[1], z = pp[2];
        float p2 = x * x + y * y + z * z;

        float d0 = 3.4e38f, d1 = 3.4e38f, d2 = 3.4e38f;
        int   j0 = 0, j1 = 0, j2 = 0;
        #pragma unroll 4
        for (int m = 0; m < N2_; m++) {
            float4 v = s2[m];
            float dot = x * v.x + y * v.y + z * v.z;
            float dd  = (p2 + v.w) - 2.0f * dot;
            if (dd < d2) {
                if (dd < d1) {
                    d2 = d1; j2 = j1;
                    if (dd < d0) { d1 = d0; j1 = j0; d0 = dd; j0 = m; }
                    else         { d1 = dd; j1 = m; }
                } else { d2 = dd; j2 = m; }
            }
        }
        float r0 = sqrtf(fmaxf(d0, 0.f));
        float r1 = sqrtf(fmaxf(d1, 0.f));
        float r2 = sqrtf(fmaxf(d2, 0.f));
        float w0 = 1.0f / fmaxf(r0, 1e-8f);
        float w1 = 1.0f / fmaxf(r1, 1e-8f);
        float w2 = 1.0f / fmaxf(r2, 1e-8f);
        float inv = 1.0f / (w0 + w1 + w2);

        size_t base = ((size_t)b * N1_ + p) * 3;
        g_idx[base + 0] = j0; g_idx[base + 1] = j1; g_idx[base + 2] = j2;
        g_wgt[base + 0] = w0 * inv; g_wgt[base + 1] = w1 * inv; g_wgt[base + 2] = w2 * inv;
        return;
    }

    // ---------------- gemmP v3 (R13 body, flattened indices) ----------------
    int g = blockIdx.x - KNN_BLKS;
    const int Mbase = (g & 31) * 64;
    const int nb = (g >> 5) & 1;
    const int b = g >> 6;

    const int tid = threadIdx.x, lane = tid & 31, wid = tid >> 5;
    const int warpM = wid >> 2, warpN = wid & 3;

    float acc[2][4][4];
    #pragma unroll
    for (int i = 0; i < 2; i++)
        #pragma unroll
        for (int j = 0; j < 4; j++)
            #pragma unroll
            for (int k = 0; k < 4; k++) acc[i][j][k] = 0.f;

    const size_t aB = (((size_t)b * 128 + (Mbase >> 4) + warpM * 2) * 16) * 32 + lane;

    for (int kt = 0; kt < 16; kt++) {
        uint4 afh[2], afl[2];
        #pragma unroll
        for (int mi = 0; mi < 2; mi++) {
            afh[mi] = g_f2P_hi[aB + mi * 512 + kt * 32];
            afl[mi] = g_f2P_lo[aB + mi * 512 + kt * 32];
        }
        uint4 fh[2], fl[2];
        #pragma unroll
        for (int nj = 0; nj < 2; nj++) {
            size_t o = (((size_t)(nb * 16 + kt) * 4 + warpN) * 2 + nj) * 32 + lane;
            fh[nj] = g_W1ap_hi[o];
            fl[nj] = g_W1ap_lo[o];
        }
        #pragma unroll
        for (int nj = 0; nj < 2; nj++) {
            const uint32_t* BH = (const uint32_t*)&fh[nj];
            const uint32_t* BL = (const uint32_t*)&fl[nj];
            #pragma unroll
            for (int mi = 0; mi < 2; mi++) {
                const uint32_t* AH = (const uint32_t*)&afh[mi];
                const uint32_t* AL = (const uint32_t*)&afl[mi];
                #pragma unroll
                for (int sub = 0; sub < 2; sub++) {
                    int ni = nj * 2 + sub;
                    uint32_t b0 = BH[sub * 2], b1 = BH[sub * 2 + 1];
                    uint32_t c0_ = BL[sub * 2], c1_ = BL[sub * 2 + 1];
                    mma16816(acc[mi][ni], AH, b0, b1);
                    mma16816(acc[mi][ni], AH, c0_, c1_);
                    mma16816(acc[mi][ni], AL, b0, b1);
                }
            }
        }
    }

    const int r0 = lane >> 2;
    const int c0 = (lane & 3) * 2;
    float* outP = g_PT + (size_t)b * N2_ * O1_;
    const int Nbase = nb * 128;
    #pragma unroll
    for (int mi = 0; mi < 2; mi++)
        #pragma unroll
        for (int h = 0; h < 2; h++) {
            int gm = Mbase + warpM * 32 + mi * 16 + r0 + h * 8;
            #pragma unroll
            for (int ni = 0; ni < 4; ni++) {
                int gn = Nbase + warpN * 32 + ni * 8 + c0;
                *(float2*)&outP[(size_t)gm * O1_ + gn] =
                    make_float2(acc[mi][ni][h * 2], acc[mi][ni][h * 2 + 1]);
            }
        }
}

// ============================================================
// prepsplit (unchanged from R13): feats -> A-fragment pack; weights pack
// ============================================================
#define TS1_BLKS  ((N1_ / 32) * (C1_ / 32) * B_)      // 8192
#define TS2_BLKS  ((N2_ / 32) * (C2_ / 32) * B_)      // 4096
#define PACK_BLKS 64
#define RS_ 0.99999500003749969f

__device__ __forceinline__ void tsplit_pack(int n_t, int c_t, int b,
                                            const float* __restrict__ src,
                                            uint4* __restrict__ phi, uint4* __restrict__ plo,
                                            int C, int Np, float (*t)[33]) {
    int n0 = n_t * 32, c0 = c_t * 32;
    int tx = threadIdx.x & 31, ty = threadIdx.x >> 5;
    #pragma unroll
    for (int r = 0; r < 4; r++) {
        int c = c0 + ty + r * 8;
        t[ty + r * 8][tx] = src[((size_t)b * C + c) * Np + n0 + tx];
    }
    __syncthreads();
    int i = threadIdx.x;
    if (i < 128) {
        int tile = i >> 5, lane = i & 31;
        int tn = tile & 1, tc = tile >> 1;
        uint4 h, l;
        uint32_t* hp = (uint32_t*)&h;
        uint32_t* lp = (uint32_t*)&l;
        #pragma unroll
        for (int j = 0; j < 4; j++) {
            int nl = tn * 16 + ((j & 1) << 3) + (lane >> 2);
            int cl = tc * 16 + ((j >> 1) << 3) + (lane & 3) * 2;
            hp[j] = splitpack(t[cl][nl], t[cl + 1][nl], lp[j]);
        }
        int NT = Np / 16, KT = C / 16;
        int rt = n_t * 2 + tn, kt = c_t * 2 + tc;
        size_t o = (((size_t)b * NT + rt) * KT + kt) * 32 + lane;
        phi[o] = h;
        plo[o] = l;
    }
}

__global__ void __launch_bounds__(256) prepsplit_kernel(
    const float* __restrict__ feats1, const float* __restrict__ feats2,
    const float* __restrict__ W1, const float* __restrict__ b1,
    const float* __restrict__ g1, const float* __restrict__ be1,
    const float* __restrict__ W2, const float* __restrict__ b2,
    const float* __restrict__ g2, const float* __restrict__ be2) {
    __shared__ float t[32][33];
    int bid = blockIdx.x;
    if (bid < TS1_BLKS) {
        int n_t = bid & 255, c_t = (bid >> 8) & 3, b = bid >> 10;
        tsplit_pack(n_t, c_t, b, feats1, g_f1P_hi, g_f1P_lo, C1_, N1_, t);
        return;
    }
    bid -= TS1_BLKS;
    if (bid < TS2_BLKS) {
        int n_t = bid & 63, c_t = (bid >> 6) & 7, b = bid >> 9;
        tsplit_pack(n_t, c_t, b, feats2, g_f2P_hi, g_f2P_lo, C2_, N2_, t);
        return;
    }
    bid -= TS2_BLKS;
    int tt = bid * 256 + threadIdx.x;
    int nt = PACK_BLKS * 256;
    for (int i = tt; i < 8192; i += nt) {
        int lane = i & 31, nj = (i >> 5) & 3, wN = (i >> 7) & 3, ks = (i >> 9) & 1, kc = i >> 10;
        int n0 = wN * 64 + nj * 16, k0 = kc * 32 + ks * 16;
        uint4 h, l;
        uint32_t* hp = (uint32_t*)&h;
        uint32_t* lp = (uint32_t*)&l;
        #pragma unroll
        for (int j = 0; j < 4; j++) {
            int n = n0 + ((j >> 1) << 3) + (lane >> 2);
            int k = k0 + ((j & 1) << 3) + (lane & 3) * 2;
            float s = g2[n] * RS_;
            hp[j] = fold2(W2[(size_t)n * O1_ + k], W2[(size_t)n * O1_ + k + 1], s, lp[j]);
        }
        g_W2p_hi[i] = h;
        g_W2p_lo[i] = l;
    }
    for (int i = tt; i < 4096; i += nt) {
        int lane = i & 31, nj = (i >> 5) & 3, wN = (i >> 7) & 3, ks = (i >> 9) & 1, kc = i >> 10;
        int n0 = wN * 64 + nj * 16, k0 = kc * 32 + ks * 16;
        uint4 h, l;
        uint32_t* hp = (uint32_t*)&h;
        uint32_t* lp = (uint32_t*)&l;
        #pragma unroll
        for (int j = 0; j < 4; j++) {
            int n = n0 + ((j >> 1) << 3) + (lane >> 2);
            int k = k0 + ((j & 1) << 3) + (lane & 3) * 2;
            float s = g1[n] * RS_;
            hp[j] = fold2(W1[(size_t)n * INCH + C2_ + k], W1[(size_t)n * INCH + C2_ + k + 1], s, lp[j]);
        }
        g_W1bp_hi[i] = h;
        g_W1bp_lo[i] = l;
    }
    for (int i = tt; i < 8192; i += nt) {
        int lane = i & 31, nj = (i >> 5) & 1, wN = (i >> 6) & 3, ks = (i >> 8) & 1,
            kc = (i >> 9) & 7, nb = (i >> 12) & 1;
        int n0 = nb * 128 + wN * 32 + nj * 16, k0 = kc * 32 + ks * 16;
        uint4 h, l;
        uint32_t* hp = (uint32_t*)&h;
        uint32_t* lp = (uint32_t*)&l;
        #pragma unroll
        for (int j = 0; j < 4; j++) {
            int n = n0 + ((j >> 1) << 3) + (lane >> 2);
            int k = k0 + ((j & 1) << 3) + (lane & 3) * 2;
            float s = g1[n] * RS_;
            hp[j] = fold2(W1[(size_t)n * INCH + k], W1[(size_t)n * INCH + k + 1], s, lp[j]);
        }
        g_W1ap_hi[i] = h;
        g_W1ap_lo[i] = l;
    }
    for (int i = tt; i < O1_; i += nt) g_b1eff[i] = g1[i] * RS_ * b1[i] + be1[i];
    for (int i = tt; i < O2_; i += nt) g_b2eff[i] = g2[i] * RS_ * b2[i] + be2[i];
}

// ============================================================
extern "C" void kernel_launch(void* const* d_in, const int* in_sizes, int n_in,
                              void* d_out, int out_size) {
    const float* xyz1   = (const float*)d_in[0];
    const float* xyz2   = (const float*)d_in[1];
    const float* feats1 = (const float*)d_in[2];
    const float* feats2 = (const float*)d_in[3];
    const float* W1     = (const float*)d_in[4];
    const float* b1     = (const float*)d_in[5];
    const float* g1     = (const float*)d_in[6];
    const float* be1    = (const float*)d_in[7];
    const float* W2     = (const float*)d_in[8];
    const float* b2     = (const float*)d_in[9];
    const float* g2     = (const float*)d_in[10];
    const float* be2    = (const float*)d_in[11];
    float* out = (float*)d_out;

    cudaFuncSetAttribute(fused12_kernel, cudaFuncAttributeMaxDynamicSharedMemorySize, FSM_BYTES);

    prepsplit_kernel<<<TS1_BLKS + TS2_BLKS + PACK_BLKS, 256>>>(
        feats1, feats2, W1, b1, g1, be1, W2, b2, g2, be2);            // idx 0
    knngemmP_kernel<<<KNN_BLKS + 512, 256>>>(xyz1, xyz2);             // idx 1 (knn || gemmP)
    fused12_kernel<<<dim3(N1_ / 64, B_), 256, FSM_BYTES>>>(out);      // idx 2
}